// round 8
// baseline (speedup 1.0000x reference)
#include <cuda_runtime.h>
#include <math.h>

// ---------------- problem constants ----------------
#define BATCH   64
#define SEQ     512
#define EMB     256
#define HID     512
#define GATES   2048           // 4*HID
#define VOCAB   50257
#define NBLK    128            // persistent LSTM grid (<=148 SMs, 1 block/SM)

// ---------------- device scratch (static, no allocs) ----------------
__device__ float g_Z[(size_t)SEQ * BATCH * GATES];   // 256 MB: x@Wi + b, [s][b][4H]
__device__ float g_hT[2][HID * BATCH];               // hidden state, k-major [u][b]
__device__ float g_y1[BATCH * HID];
__device__ float g_y2[BATCH * HID];
__device__ float g_logits[(size_t)BATCH * VOCAB];
__device__ unsigned g_bar_cnt   = 0;
__device__ unsigned g_bar_sense = 0;

// ---------------- packed f32x2 helpers (FFMA2 path, sm_100+) --------------
__device__ __forceinline__ unsigned long long fma2(unsigned long long a,
                                                   unsigned long long b,
                                                   unsigned long long c)
{
    unsigned long long d;
    asm("fma.rn.f32x2 %0, %1, %2, %3;" : "=l"(d) : "l"(a), "l"(b), "l"(c));
    return d;
}
__device__ __forceinline__ unsigned long long pack2(float x)
{
    unsigned long long d;
    unsigned u = __float_as_uint(x);
    asm("mov.b64 %0, {%1, %1};" : "=l"(d) : "r"(u));
    return d;
}
__device__ __forceinline__ float lo2(unsigned long long v) { return __uint_as_float((unsigned)v); }
__device__ __forceinline__ float hi2(unsigned long long v) { return __uint_as_float((unsigned)(v >> 32)); }

// ---------------- fast activations (MUFU.TANH) ----------------
__device__ __forceinline__ float tanh_fast(float x)
{
    float y;
    asm("tanh.approx.f32 %0, %1;" : "=f"(y) : "f"(x));
    return y;
}
__device__ __forceinline__ float sigmoid_fast(float x)
{
    return 0.5f * tanh_fast(0.5f * x) + 0.5f;
}

// ---------------- cp.async helpers ----------------
__device__ __forceinline__ void cp16(unsigned dst_u32, const void* src)
{
    asm volatile("cp.async.cg.shared.global [%0], [%1], 16;"
                 :: "r"(dst_u32), "l"(src) : "memory");
}
__device__ __forceinline__ void cp_commit()
{
    asm volatile("cp.async.commit_group;" ::: "memory");
}
__device__ __forceinline__ void cp_wait0()
{
    asm volatile("cp.async.wait_group 0;" ::: "memory");
}

// ---------------- grid barrier: release/acquire, single poller ------------
__device__ __forceinline__ void grid_barrier(unsigned &sense)
{
    __syncthreads();
    if (threadIdx.x == 0) {
        sense ^= 1u;
        unsigned old;
        asm volatile("atom.add.release.gpu.global.u32 %0, [%1], %2;"
                     : "=r"(old) : "l"(&g_bar_cnt), "r"(1u) : "memory");
        if (old == NBLK - 1u) {
            asm volatile("st.global.relaxed.gpu.u32 [%0], %1;"
                         :: "l"(&g_bar_cnt), "r"(0u) : "memory");
            asm volatile("st.global.release.gpu.u32 [%0], %1;"
                         :: "l"(&g_bar_sense), "r"(sense) : "memory");
        } else {
            unsigned v;
            do {
                asm volatile("ld.global.acquire.gpu.u32 %0, [%1];"
                             : "=r"(v) : "l"(&g_bar_sense) : "memory");
            } while (v != sense);
        }
    }
    __syncthreads();
}

// ---------------- kernel 1: Z = gather(emb, inputs) @ Wi + b --------------
// (R2-proven, unchanged) 128x128 tile, K-chunks of 16, 8x8 thread tile, f32x2.
__global__ void __launch_bounds__(256, 2)
embed_gemm_kernel(const int* __restrict__ inputs, const float* __restrict__ emb,
                  const float* __restrict__ Wi, const float* __restrict__ bias)
{
    __shared__ float As[128][17];
    __shared__ float Bs[16][132];

    const int t  = threadIdx.x;
    const int mt = blockIdx.y;
    const int nt = blockIdx.x;
    const int tx = t & 15;
    const int ty = t >> 4;

    const int ra   = t >> 1;
    const int koff = (t & 1) * 8;
    const int rowg = mt * 128 + ra;
    const int s    = rowg >> 6;
    const int b    = rowg & 63;
    const float* erow = emb + (size_t)inputs[b * SEQ + s] * EMB;

    const int bkr  = t >> 4;
    const int bcol = (t & 15) * 8;

    unsigned long long acc[8][4];
#pragma unroll
    for (int i = 0; i < 8; ++i)
#pragma unroll
        for (int j = 0; j < 4; ++j) acc[i][j] = 0ULL;

    for (int k0 = 0; k0 < EMB; k0 += 16) {
        {
            float4 a0 = *(const float4*)(erow + k0 + koff);
            float4 a1 = *(const float4*)(erow + k0 + koff + 4);
            As[ra][koff + 0] = a0.x; As[ra][koff + 1] = a0.y;
            As[ra][koff + 2] = a0.z; As[ra][koff + 3] = a0.w;
            As[ra][koff + 4] = a1.x; As[ra][koff + 5] = a1.y;
            As[ra][koff + 6] = a1.z; As[ra][koff + 7] = a1.w;
        }
        {
            const float* wsrc = Wi + (size_t)(k0 + bkr) * GATES + nt * 128 + bcol;
            float4 b0v = *(const float4*)(wsrc);
            float4 b1v = *(const float4*)(wsrc + 4);
            *(float4*)&Bs[bkr][bcol]     = b0v;
            *(float4*)&Bs[bkr][bcol + 4] = b1v;
        }
        __syncthreads();

#pragma unroll
        for (int k = 0; k < 16; ++k) {
            unsigned long long pa[8];
#pragma unroll
            for (int i = 0; i < 4; ++i) {
                pa[i]     = pack2(As[ty * 4 + i][k]);
                pa[i + 4] = pack2(As[64 + ty * 4 + i][k]);
            }
            ulonglong2 b0v = *(const ulonglong2*)&Bs[k][tx * 4];
            ulonglong2 b1v = *(const ulonglong2*)&Bs[k][64 + tx * 4];
#pragma unroll
            for (int i = 0; i < 8; ++i) {
                acc[i][0] = fma2(pa[i], b0v.x, acc[i][0]);
                acc[i][1] = fma2(pa[i], b0v.y, acc[i][1]);
                acc[i][2] = fma2(pa[i], b1v.x, acc[i][2]);
                acc[i][3] = fma2(pa[i], b1v.y, acc[i][3]);
            }
        }
        __syncthreads();
    }

    float4 bb0 = *(const float4*)(bias + nt * 128 + tx * 4);
    float4 bb1 = *(const float4*)(bias + nt * 128 + 64 + tx * 4);
#pragma unroll
    for (int i = 0; i < 8; ++i) {
        int row = mt * 128 + ((i < 4) ? (ty * 4 + i) : (64 + ty * 4 + i - 4));
        float* zr = g_Z + (size_t)row * GATES + nt * 128;
        float4 v0, v1;
        v0.x = lo2(acc[i][0]) + bb0.x; v0.y = hi2(acc[i][0]) + bb0.y;
        v0.z = lo2(acc[i][1]) + bb0.z; v0.w = hi2(acc[i][1]) + bb0.w;
        v1.x = lo2(acc[i][2]) + bb1.x; v1.y = hi2(acc[i][2]) + bb1.y;
        v1.z = lo2(acc[i][3]) + bb1.z; v1.w = hi2(acc[i][3]) + bb1.w;
        *(float4*)(zr + tx * 4)      = v0;
        *(float4*)(zr + 64 + tx * 4) = v1;
    }
}

// ---------------- kernel 2: persistent LSTM over 512 steps ----------------
// 128 blocks = 64 unit-groups x 2 batch-halves; block = 8 units x 32 batches.
// 512 threads = 16 warps (4/SMSP). WARP = one kc strip of 32 k (k fixed per
// inner iteration -> all LDS broadcast, conflict-free; R7-proven layout).
// Lanes = (up 0..3) x (bg 0..7); thread tile = 2 units x 4 batches x 32 k.
// Staging: two-phase cp.async with per-thread groups — threads owning the
// first half of every strip wait first; second half lands under compute.
// kc reduction via skewed smem red[p*17+kc]; epilogue thread = pair p (<256).
#define LSTM_SMEM (65536 + 65536 + 69632)

__global__ void __launch_bounds__(512, 1)
lstm_kernel(const float* __restrict__ Wh)
{
    extern __shared__ float sm[];
    float4*     h_s4 = (float4*)sm;                           // [512][8] (64KB)
    ulonglong2* Whs  = (ulonglong2*)((char*)sm + 65536);      // [512][8] (64KB)
    ulonglong2* red  = (ulonglong2*)((char*)sm + 131072);     // [256 p][17] skew

    const int tid  = threadIdx.x;
    const int kc   = tid >> 5;           // warp id = k-strip 0..15 (32 k each)
    const int lane = tid & 31;
    const int up   = (lane >> 3) & 3;    // unit pair 0..3 (units 2up, 2up+1)
    const int bg   = lane & 7;           // batch group 0..7 (4 batches)
    const int ub   = blockIdx.x >> 1;    // unit group 0..63
    const int bh   = blockIdx.x & 1;     // batch half
    const unsigned h_s_u32 = (unsigned)__cvta_generic_to_shared(h_s4);

    // epilogue ownership: pair p = tid (<256) -> unit eu, local batch ebl
    const int eu  = tid >> 5;            // 0..7 (tid<256)
    const int ebl = tid & 31;            // 0..31
    const int euu = ub * 8 + eu;
    const int egb = bh * 32 + ebl;

    // phase membership for staging: this thread's 8 chunks are all in the
    // first half of their strips iff ((tid>>3)&31) < 16.
    const bool phaseA = (((tid >> 3) & 31) < 16);

    // stage Wh slice once: Whs[k*8+u] = {(wi,wf),(wg,wo)} for col = ub*8+u
    for (int i = tid; i < HID * 8; i += 512) {
        int k = i >> 3, u2 = i & 7;
        const float* w = Wh + (size_t)k * GATES + ub * 8 + u2;
        float4 v = make_float4(w[0], w[512], w[1024], w[1536]);
        Whs[i] = *(ulonglong2*)&v;
    }

    float c = 0.0f;                      // cell state of pair p = tid (<256)
    unsigned sense = 0;
    __syncthreads();

    const ulonglong2* wp = Whs  + kc * 256 + up * 2;   // iter i: wp[i*8], wp[i*8+1]
    const float4*     hp = h_s4 + kc * 256 + bg;       // iter i: hp[i*8]

    // Z prefetch for step 0 (gates for pair p)
    float zi = 0.f, zf = 0.f, zg = 0.f, zo = 0.f;
    if (tid < 256) {
        const float* z0 = g_Z + (size_t)egb * GATES + euu;
        zi = __ldcg(z0);        zf = __ldcg(z0 + 512);
        zg = __ldcg(z0 + 1024); zo = __ldcg(z0 + 1536);
    }

    for (int s = 0; s < SEQ; ++s) {
        // ---- two-phase cp.async staging of h_{s-1} ----
        if (s > 0) {
            const float4* src4 = (const float4*)g_hT[s & 1];
#pragma unroll
            for (int j = 0; j < 8; ++j) {
                int chunk = tid + j * 512;                 // 0..4095
                cp16(h_s_u32 + chunk * 16,
                     src4 + (chunk >> 3) * 16 + bh * 8 + (chunk & 7));
            }
            cp_commit();
            if (phaseA) cp_wait0();       // only first-half owners wait now
        }
        __syncthreads();   // first half of every strip visible

        unsigned long long aif[2][4] = {{0,0,0,0},{0,0,0,0}};
        unsigned long long ago[2][4] = {{0,0,0,0},{0,0,0,0}};

        if (s > 0) {
            // compute first half of strip (i = 0..15); phase B still landing
#pragma unroll 4
            for (int i = 0; i < 16; ++i) {
                ulonglong2 w0 = wp[i * 8];
                ulonglong2 w1 = wp[i * 8 + 1];
                float4     hv = hp[i * 8];
                unsigned long long p;
                p = pack2(hv.x);
                aif[0][0] = fma2(p, w0.x, aif[0][0]); ago[0][0] = fma2(p, w0.y, ago[0][0]);
                aif[1][0] = fma2(p, w1.x, aif[1][0]); ago[1][0] = fma2(p, w1.y, ago[1][0]);
                p = pack2(hv.y);
                aif[0][1] = fma2(p, w0.x, aif[0][1]); ago[0][1] = fma2(p, w0.y, ago[0][1]);
                aif[1][1] = fma2(p, w1.x, aif[1][1]); ago[1][1] = fma2(p, w1.y, ago[1][1]);
                p = pack2(hv.z);
                aif[0][2] = fma2(p, w0.x, aif[0][2]); ago[0][2] = fma2(p, w0.y, ago[0][2]);
                aif[1][2] = fma2(p, w1.x, aif[1][2]); ago[1][2] = fma2(p, w1.y, ago[1][2]);
                p = pack2(hv.w);
                aif[0][3] = fma2(p, w0.x, aif[0][3]); ago[0][3] = fma2(p, w0.y, ago[0][3]);
                aif[1][3] = fma2(p, w1.x, aif[1][3]); ago[1][3] = fma2(p, w1.y, ago[1][3]);
            }
            if (!phaseA) cp_wait0();      // second-half owners drain their group
        }
        __syncthreads();   // second half visible

        if (s > 0) {
#pragma unroll 4
            for (int i = 16; i < 32; ++i) {
                ulonglong2 w0 = wp[i * 8];
                ulonglong2 w1 = wp[i * 8 + 1];
                float4     hv = hp[i * 8];
                unsigned long long p;
                p = pack2(hv.x);
                aif[0][0] = fma2(p, w0.x, aif[0][0]); ago[0][0] = fma2(p, w0.y, ago[0][0]);
                aif[1][0] = fma2(p, w1.x, aif[1][0]); ago[1][0] = fma2(p, w1.y, ago[1][0]);
                p = pack2(hv.y);
                aif[0][1] = fma2(p, w0.x, aif[0][1]); ago[0][1] = fma2(p, w0.y, ago[0][1]);
                aif[1][1] = fma2(p, w1.x, aif[1][1]); ago[1][1] = fma2(p, w1.y, ago[1][1]);
                p = pack2(hv.z);
                aif[0][2] = fma2(p, w0.x, aif[0][2]); ago[0][2] = fma2(p, w0.y, ago[0][2]);
                aif[1][2] = fma2(p, w1.x, aif[1][2]); ago[1][2] = fma2(p, w1.y, ago[1][2]);
                p = pack2(hv.w);
                aif[0][3] = fma2(p, w0.x, aif[0][3]); ago[0][3] = fma2(p, w0.y, ago[0][3]);
                aif[1][3] = fma2(p, w1.x, aif[1][3]); ago[1][3] = fma2(p, w1.y, ago[1][3]);
            }
        }

        // ---- write partials to skewed red[p*17 + kc] ----
#pragma unroll
        for (int uo = 0; uo < 2; ++uo)
#pragma unroll
            for (int bi = 0; bi < 4; ++bi) {
                int p = (2 * up + uo) * 32 + bg * 4 + bi;
                red[p * 17 + kc] = make_ulonglong2(aif[uo][bi], ago[uo][bi]);
            }
        __syncthreads();

        // ---- reduce 16 kc partials for pair p = tid (<256); epilogue ----
        if (tid < 256) {
            float fi = zi, ff = zf, fg_ = zg, fo = zo;
#pragma unroll
            for (int k16 = 0; k16 < 16; ++k16) {
                ulonglong2 v = red[tid * 17 + k16];
                fi += lo2(v.x); ff += hi2(v.x);
                fg_ += lo2(v.y); fo += hi2(v.y);
            }
            float ig  = sigmoid_fast(fi);
            float fg2 = sigmoid_fast(ff);
            float gg  = tanh_fast(fg_);
            float og  = sigmoid_fast(fo);
            c = fg2 * c + ig * gg;
            float hv = og * tanh_fast(c);
            g_hT[(s + 1) & 1][euu * 64 + egb] = hv;    // final h in g_hT[0]

            // prefetch Z for step s+1 (hides DRAM latency behind barrier)
            if (s + 1 < SEQ) {
                const float* z = g_Z + ((size_t)(s + 1) * BATCH + egb) * GATES + euu;
                zi = __ldcg(z);        zf = __ldcg(z + 512);
                zg = __ldcg(z + 1024); zo = __ldcg(z + 1536);
            }
        }

        grid_barrier(sense);
    }
}

// ---------------- kernels 3/4: y = tanh(x @ W + bias), 64x512 --------------
template<int SK, int SB>
__global__ void __launch_bounds__(256)
fc_tanh_kernel(const float* __restrict__ x, const float* __restrict__ W,
               const float* __restrict__ bias, float* __restrict__ y)
{
    int o = blockIdx.x * blockDim.x + threadIdx.x;
    int b = o >> 9, j = o & 511;
    const float* xp = x + b * SB;
    float a0 = 0.f, a1 = 0.f, a2 = 0.f, a3 = 0.f;
#pragma unroll 4
    for (int k = 0; k < HID; k += 4) {
        a0 += xp[(k + 0) * SK] * W[(size_t)(k + 0) * HID + j];
        a1 += xp[(k + 1) * SK] * W[(size_t)(k + 1) * HID + j];
        a2 += xp[(k + 2) * SK] * W[(size_t)(k + 2) * HID + j];
        a3 += xp[(k + 3) * SK] * W[(size_t)(k + 3) * HID + j];
    }
    y[o] = tanhf((a0 + a1) + (a2 + a3) + bias[j]);
}

// ---------------- kernel 5: logits = y2 @ W3 + b3 ----------------
__global__ void __launch_bounds__(128)
logits_kernel(const float* __restrict__ y, const float* __restrict__ W3,
              const float* __restrict__ b3, float* __restrict__ out)
{
    __shared__ float ys[128][68];
    const int j = blockIdx.x * 128 + threadIdx.x;

    float acc[64];
#pragma unroll
    for (int b = 0; b < 64; ++b) acc[b] = 0.0f;

    for (int kc = 0; kc < HID; kc += 128) {
        __syncthreads();
        for (int q = threadIdx.x; q < 128 * 64; q += 128) {
            int b = q >> 7, k = q & 127;
            ys[k][b] = y[b * HID + kc + k];
        }
        __syncthreads();
        if (j < VOCAB) {
#pragma unroll 4
            for (int k = 0; k < 128; ++k) {
                float w = W3[(size_t)(kc + k) * VOCAB + j];
                const float4* yr = (const float4*)&ys[k][0];
#pragma unroll
                for (int b4 = 0; b4 < 16; ++b4) {
                    float4 v = yr[b4];
                    acc[b4 * 4 + 0] += v.x * w;
                    acc[b4 * 4 + 1] += v.y * w;
                    acc[b4 * 4 + 2] += v.z * w;
                    acc[b4 * 4 + 3] += v.w * w;
                }
            }
        }
    }
    if (j < VOCAB) {
        float bb = b3[j];
#pragma unroll
        for (int b = 0; b < 64; ++b)
            out[(size_t)b * VOCAB + j] = acc[b] + bb;
    }
}

// ---------------- kernel 6: row-wise log_softmax ----------------
__global__ void __launch_bounds__(1024)
logsoftmax_kernel(const float* __restrict__ logits, float* __restrict__ out)
{
    __shared__ float red[32];
    const int b = blockIdx.x;
    const float* row  = logits + (size_t)b * VOCAB;
    float*       orow = out    + (size_t)b * VOCAB;
    const int tid = threadIdx.x;

    float m = -1e30f;
    for (int j = tid; j < VOCAB; j += 1024) m = fmaxf(m, row[j]);
#pragma unroll
    for (int o = 16; o; o >>= 1) m = fmaxf(m, __shfl_xor_sync(0xffffffffu, m, o));
    if ((tid & 31) == 0) red[tid >> 5] = m;
    __syncthreads();
    if (tid < 32) {
        float v = red[tid];
#pragma unroll
        for (int o = 16; o; o >>= 1) v = fmaxf(v, __shfl_xor_sync(0xffffffffu, v, o));
        red[tid] = v;
    }
    __syncthreads();
    m = red[0];

    float sum = 0.0f;
    for (int j = tid; j < VOCAB; j += 1024) sum += __expf(row[j] - m);
#pragma unroll
    for (int o = 16; o; o >>= 1) sum += __shfl_xor_sync(0xffffffffu, sum, o);
    __syncthreads();
    if ((tid & 31) == 0) red[tid >> 5] = sum;
    __syncthreads();
    if (tid < 32) {
        float v = red[tid];
#pragma unroll
        for (int o = 16; o; o >>= 1) v += __shfl_xor_sync(0xffffffffu, v, o);
        red[tid] = v;
    }
    __syncthreads();
    float lse = m + logf(red[0]);

    for (int j = tid; j < VOCAB; j += 1024) orow[j] = row[j] - lse;
}

// ---------------- launch ----------------
extern "C" void kernel_launch(void* const* d_in, const int* in_sizes, int n_in,
                              void* d_out, int out_size)
{
    const int*   inputs = (const int*)  d_in[0];
    const float* emb    = (const float*)d_in[1];
    const float* Wi     = (const float*)d_in[2];
    const float* Wh     = (const float*)d_in[3];
    const float* bvec   = (const float*)d_in[4];
    const float* W1     = (const float*)d_in[5];
    const float* b1     = (const float*)d_in[6];
    const float* W2     = (const float*)d_in[7];
    const float* b2     = (const float*)d_in[8];
    const float* W3     = (const float*)d_in[9];
    const float* b3     = (const float*)d_in[10];
    float* out = (float*)d_out;

    void *p_h = 0, *p_y1 = 0, *p_y2 = 0, *p_lg = 0;
    cudaGetSymbolAddress(&p_h,  g_hT);     // final h in g_hT[0], k-major [u][b]
    cudaGetSymbolAddress(&p_y1, g_y1);
    cudaGetSymbolAddress(&p_y2, g_y2);
    cudaGetSymbolAddress(&p_lg, g_logits);

    // 1. Z = emb[inputs] @ Wi + b  (time-parallel)
    embed_gemm_kernel<<<dim3(GATES / 128, (SEQ * BATCH) / 128), 256>>>(inputs, emb, Wi, bvec);

    // 2. persistent LSTM recurrence
    cudaFuncSetAttribute(lstm_kernel, cudaFuncAttributeMaxDynamicSharedMemorySize, LSTM_SMEM);
    lstm_kernel<<<NBLK, 512, LSTM_SMEM>>>(Wh);

    // 3/4. dense tanh layers (fc1 reads k-major h)
    fc_tanh_kernel<64, 1><<<128, 256>>>((const float*)p_h,  W1, b1, (float*)p_y1);
    fc_tanh_kernel<1, 512><<<128, 256>>>((const float*)p_y1, W2, b2, (float*)p_y2);

    // 5. vocab projection
    logits_kernel<<<(VOCAB + 127) / 128, 128>>>((const float*)p_y2, W3, b3, (float*)p_lg);

    // 6. log_softmax
    logsoftmax_kernel<<<BATCH, 1024>>>((const float*)p_lg, out);
}

// round 9
// speedup vs baseline: 1.0285x; 1.0285x over previous
#include <cuda_runtime.h>
#include <math.h>

// ---------------- problem constants ----------------
#define BATCH   64
#define SEQ     512
#define EMB     256
#define HID     512
#define GATES   2048           // 4*HID
#define VOCAB   50257
#define NBLK    128            // persistent LSTM grid (<=148 SMs, 1 block/SM)

// ---------------- device scratch (static, no allocs) ----------------
__device__ float g_Z[(size_t)SEQ * BATCH * GATES];   // 256 MB: x@Wi + b, [s][b][4H]
__device__ float g_hT[2][HID * BATCH];               // hidden state, k-major [u][b]
__device__ float g_y1[BATCH * HID];
__device__ float g_y2[BATCH * HID];
__device__ float g_logits[(size_t)BATCH * VOCAB];
// hierarchical barrier state: 16 leaf counters (8 blocks each), 2 roots, 2 flags
// each on its own 128B line; monotonic counts, zeroed by reset_kernel per launch
__device__ unsigned g_leaf[16 * 32];
__device__ unsigned g_root[2 * 32];
__device__ unsigned g_flag[2 * 32];

// ---------------- packed f32x2 helpers (FFMA2 path, sm_100+) --------------
__device__ __forceinline__ unsigned long long fma2(unsigned long long a,
                                                   unsigned long long b,
                                                   unsigned long long c)
{
    unsigned long long d;
    asm("fma.rn.f32x2 %0, %1, %2, %3;" : "=l"(d) : "l"(a), "l"(b), "l"(c));
    return d;
}
__device__ __forceinline__ unsigned long long pack2(float x)
{
    unsigned long long d;
    unsigned u = __float_as_uint(x);
    asm("mov.b64 %0, {%1, %1};" : "=l"(d) : "r"(u));
    return d;
}
__device__ __forceinline__ float lo2(unsigned long long v) { return __uint_as_float((unsigned)v); }
__device__ __forceinline__ float hi2(unsigned long long v) { return __uint_as_float((unsigned)(v >> 32)); }

// ---------------- fast activations (MUFU.TANH) ----------------
__device__ __forceinline__ float tanh_fast(float x)
{
    float y;
    asm("tanh.approx.f32 %0, %1;" : "=f"(y) : "f"(x));
    return y;
}
__device__ __forceinline__ float sigmoid_fast(float x)
{
    return 0.5f * tanh_fast(0.5f * x) + 0.5f;
}

// ---------------- cp.async helpers ----------------
__device__ __forceinline__ void cp16(unsigned dst_u32, const void* src)
{
    asm volatile("cp.async.cg.shared.global [%0], [%1], 16;"
                 :: "r"(dst_u32), "l"(src) : "memory");
}
__device__ __forceinline__ void cp_commit()
{
    asm volatile("cp.async.commit_group;" ::: "memory");
}
__device__ __forceinline__ void cp_wait0()
{
    asm volatile("cp.async.wait_group 0;" ::: "memory");
}

// ---- hierarchical per-bh grid barrier (monotonic counters, acq_rel chain) --
// 64 blocks per bh group: 8 leaves x 8 blocks -> 1 root -> 1 release flag.
// Max same-address atomic concurrency = 8 (was 128) -> ~0.5K cyc arrival.
__device__ __forceinline__ void grid_barrier_h(int s, unsigned* leaf,
                                               unsigned* root, unsigned* flag)
{
    __syncthreads();
    if (threadIdx.x == 0) {
        const unsigned tgt = (unsigned)(s * 8 + 7);
        unsigned old;
        asm volatile("atom.add.acq_rel.gpu.global.u32 %0, [%1], %2;"
                     : "=r"(old) : "l"(leaf), "r"(1u) : "memory");
        if (old == tgt) {
            unsigned old2;
            asm volatile("atom.add.acq_rel.gpu.global.u32 %0, [%1], %2;"
                         : "=r"(old2) : "l"(root), "r"(1u) : "memory");
            if (old2 == tgt) {
                asm volatile("st.global.release.gpu.u32 [%0], %1;"
                             :: "l"(flag), "r"((unsigned)(s + 1)) : "memory");
            }
        }
        unsigned v;
        do {
            asm volatile("ld.global.acquire.gpu.u32 %0, [%1];"
                         : "=r"(v) : "l"(flag) : "memory");
        } while (v < (unsigned)(s + 1));
    }
    __syncthreads();
}

// ---------------- kernel 0: reset barrier state (per launch, replay-safe) --
__global__ void reset_kernel()
{
    int t = threadIdx.x;
    if (t < 16 * 32) g_leaf[t] = 0u;
    if (t < 2 * 32)  { g_root[t] = 0u; g_flag[t] = 0u; }
}

// ---------------- kernel 1: Z = gather(emb, inputs) @ Wi + b --------------
// (R2-proven, unchanged) 128x128 tile, K-chunks of 16, 8x8 thread tile, f32x2.
__global__ void __launch_bounds__(256, 2)
embed_gemm_kernel(const int* __restrict__ inputs, const float* __restrict__ emb,
                  const float* __restrict__ Wi, const float* __restrict__ bias)
{
    __shared__ float As[128][17];
    __shared__ float Bs[16][132];

    const int t  = threadIdx.x;
    const int mt = blockIdx.y;
    const int nt = blockIdx.x;
    const int tx = t & 15;
    const int ty = t >> 4;

    const int ra   = t >> 1;
    const int koff = (t & 1) * 8;
    const int rowg = mt * 128 + ra;
    const int s    = rowg >> 6;
    const int b    = rowg & 63;
    const float* erow = emb + (size_t)inputs[b * SEQ + s] * EMB;

    const int bkr  = t >> 4;
    const int bcol = (t & 15) * 8;

    unsigned long long acc[8][4];
#pragma unroll
    for (int i = 0; i < 8; ++i)
#pragma unroll
        for (int j = 0; j < 4; ++j) acc[i][j] = 0ULL;

    for (int k0 = 0; k0 < EMB; k0 += 16) {
        {
            float4 a0 = *(const float4*)(erow + k0 + koff);
            float4 a1 = *(const float4*)(erow + k0 + koff + 4);
            As[ra][koff + 0] = a0.x; As[ra][koff + 1] = a0.y;
            As[ra][koff + 2] = a0.z; As[ra][koff + 3] = a0.w;
            As[ra][koff + 4] = a1.x; As[ra][koff + 5] = a1.y;
            As[ra][koff + 6] = a1.z; As[ra][koff + 7] = a1.w;
        }
        {
            const float* wsrc = Wi + (size_t)(k0 + bkr) * GATES + nt * 128 + bcol;
            float4 b0v = *(const float4*)(wsrc);
            float4 b1v = *(const float4*)(wsrc + 4);
            *(float4*)&Bs[bkr][bcol]     = b0v;
            *(float4*)&Bs[bkr][bcol + 4] = b1v;
        }
        __syncthreads();

#pragma unroll
        for (int k = 0; k < 16; ++k) {
            unsigned long long pa[8];
#pragma unroll
            for (int i = 0; i < 4; ++i) {
                pa[i]     = pack2(As[ty * 4 + i][k]);
                pa[i + 4] = pack2(As[64 + ty * 4 + i][k]);
            }
            ulonglong2 b0v = *(const ulonglong2*)&Bs[k][tx * 4];
            ulonglong2 b1v = *(const ulonglong2*)&Bs[k][64 + tx * 4];
#pragma unroll
            for (int i = 0; i < 8; ++i) {
                acc[i][0] = fma2(pa[i], b0v.x, acc[i][0]);
                acc[i][1] = fma2(pa[i], b0v.y, acc[i][1]);
                acc[i][2] = fma2(pa[i], b1v.x, acc[i][2]);
                acc[i][3] = fma2(pa[i], b1v.y, acc[i][3]);
            }
        }
        __syncthreads();
    }

    float4 bb0 = *(const float4*)(bias + nt * 128 + tx * 4);
    float4 bb1 = *(const float4*)(bias + nt * 128 + 64 + tx * 4);
#pragma unroll
    for (int i = 0; i < 8; ++i) {
        int row = mt * 128 + ((i < 4) ? (ty * 4 + i) : (64 + ty * 4 + i - 4));
        float* zr = g_Z + (size_t)row * GATES + nt * 128;
        float4 v0, v1;
        v0.x = lo2(acc[i][0]) + bb0.x; v0.y = hi2(acc[i][0]) + bb0.y;
        v0.z = lo2(acc[i][1]) + bb0.z; v0.w = hi2(acc[i][1]) + bb0.w;
        v1.x = lo2(acc[i][2]) + bb1.x; v1.y = hi2(acc[i][2]) + bb1.y;
        v1.z = lo2(acc[i][3]) + bb1.z; v1.w = hi2(acc[i][3]) + bb1.w;
        *(float4*)(zr + tx * 4)      = v0;
        *(float4*)(zr + 64 + tx * 4) = v1;
    }
}

// ---------------- kernel 2: persistent LSTM over 512 steps ----------------
// (R7-proven core, unchanged) 128 blocks = 64 unit-groups x 2 batch-halves;
// block = 8 units x 32 batches; 256 threads = 8 warps; WARP = one kc strip
// (k fixed per iteration -> all LDS broadcast, conflict-free).
// Only change vs R7: hierarchical per-bh barrier (see grid_barrier_h).
#define LSTM_SMEM (65536 + 65536 + 36864)

__global__ void __launch_bounds__(256, 1)
lstm_kernel(const float* __restrict__ Wh)
{
    extern __shared__ float sm[];
    float4*     h_s4 = (float4*)sm;                           // [512][8] (64KB)
    ulonglong2* Whs  = (ulonglong2*)((char*)sm + 65536);      // [512][8] (64KB)
    ulonglong2* red  = (ulonglong2*)((char*)sm + 131072);     // [256 p][9] skew

    const int tid = threadIdx.x;
    const int kc  = tid >> 5;            // warp id = k-strip 0..7
    const int up  = (tid >> 3) & 3;      // unit pair 0..3 (units 2up, 2up+1)
    const int bg  = tid & 7;             // batch group 0..7 (4 batches)
    const int ub  = blockIdx.x >> 1;     // unit group 0..63
    const int bh  = blockIdx.x & 1;      // batch half
    const unsigned h_s_u32 = (unsigned)__cvta_generic_to_shared(h_s4);

    // barrier addresses for this block's bh group
    unsigned* leafp = &g_leaf[(bh * 8 + (ub >> 3)) * 32];
    unsigned* rootp = &g_root[bh * 32];
    unsigned* flagp = &g_flag[bh * 32];

    // epilogue ownership: pair p = tid -> unit eu, local batch ebl
    const int eu  = tid >> 5;            // 0..7
    const int ebl = tid & 31;            // 0..31
    const int euu = ub * 8 + eu;
    const int egb = bh * 32 + ebl;

    // stage Wh slice once: Whs[k*8+u] = {(wi,wf),(wg,wo)} for col = ub*8+u
    for (int i = tid; i < HID * 8; i += 256) {
        int k = i >> 3, u2 = i & 7;
        const float* w = Wh + (size_t)k * GATES + ub * 8 + u2;
        float4 v = make_float4(w[0], w[512], w[1024], w[1536]);
        Whs[i] = *(ulonglong2*)&v;
    }

    float c = 0.0f;                      // cell state of pair p = tid
    __syncthreads();

    const ulonglong2* wp = Whs  + kc * 512 + up * 2;   // iter i: wp[i*8], wp[i*8+1]
    const float4*     hp = h_s4 + kc * 512 + bg;       // iter i: hp[i*8]

    // Z prefetch for step 0 (gates for pair p)
    const float* z0 = g_Z + (size_t)egb * GATES + euu;
    float zi = __ldcg(z0), zf = __ldcg(z0 + 512);
    float zg = __ldcg(z0 + 1024), zo = __ldcg(z0 + 1536);

    for (int s = 0; s < SEQ; ++s) {
        // ---- single-phase cp.async staging of h_{s-1} (64KB, coalesced) ----
        if (s > 0) {
            const float4* src4 = (const float4*)g_hT[s & 1];
#pragma unroll
            for (int j = 0; j < 16; ++j) {
                int chunk = tid + j * 256;                 // 0..4095
                int k = chunk >> 3, bgc = chunk & 7;
                cp16(h_s_u32 + chunk * 16, src4 + k * 16 + bh * 8 + bgc);
            }
            cp_commit();
            cp_wait0();
        }
        __syncthreads();   // h_s ready (and red from prev step fully consumed)

        unsigned long long aif[2][4] = {{0,0,0,0},{0,0,0,0}};
        unsigned long long ago[2][4] = {{0,0,0,0},{0,0,0,0}};

        if (s > 0) {
#pragma unroll 4
            for (int i = 0; i < 64; ++i) {
                ulonglong2 w0 = wp[i * 8];       // unit 2up   (wi,wf),(wg,wo)
                ulonglong2 w1 = wp[i * 8 + 1];   // unit 2up+1
                float4     hv = hp[i * 8];       // 4 batches
                unsigned long long p;
                p = pack2(hv.x);
                aif[0][0] = fma2(p, w0.x, aif[0][0]); ago[0][0] = fma2(p, w0.y, ago[0][0]);
                aif[1][0] = fma2(p, w1.x, aif[1][0]); ago[1][0] = fma2(p, w1.y, ago[1][0]);
                p = pack2(hv.y);
                aif[0][1] = fma2(p, w0.x, aif[0][1]); ago[0][1] = fma2(p, w0.y, ago[0][1]);
                aif[1][1] = fma2(p, w1.x, aif[1][1]); ago[1][1] = fma2(p, w1.y, ago[1][1]);
                p = pack2(hv.z);
                aif[0][2] = fma2(p, w0.x, aif[0][2]); ago[0][2] = fma2(p, w0.y, ago[0][2]);
                aif[1][2] = fma2(p, w1.x, aif[1][2]); ago[1][2] = fma2(p, w1.y, ago[1][2]);
                p = pack2(hv.w);
                aif[0][3] = fma2(p, w0.x, aif[0][3]); ago[0][3] = fma2(p, w0.y, ago[0][3]);
                aif[1][3] = fma2(p, w1.x, aif[1][3]); ago[1][3] = fma2(p, w1.y, ago[1][3]);
            }
        }

        // ---- write partials to skewed red[p*9 + kc] ----
#pragma unroll
        for (int uo = 0; uo < 2; ++uo)
#pragma unroll
            for (int bi = 0; bi < 4; ++bi) {
                int p = (2 * up + uo) * 32 + bg * 4 + bi;
                red[p * 9 + kc] = make_ulonglong2(aif[uo][bi], ago[uo][bi]);
            }
        __syncthreads();

        // ---- reduce 8 kc partials for pair p = tid; epilogue ----
        {
            float fi = zi, ff = zf, fg_ = zg, fo = zo;
#pragma unroll
            for (int k8 = 0; k8 < 8; ++k8) {
                ulonglong2 v = red[tid * 9 + k8];
                fi += lo2(v.x); ff += hi2(v.x);
                fg_ += lo2(v.y); fo += hi2(v.y);
            }
            float ig  = sigmoid_fast(fi);
            float fg2 = sigmoid_fast(ff);
            float gg  = tanh_fast(fg_);
            float og  = sigmoid_fast(fo);
            c = fg2 * c + ig * gg;
            float hv = og * tanh_fast(c);
            g_hT[(s + 1) & 1][euu * 64 + egb] = hv;    // final h in g_hT[0]
        }

        // ---- prefetch Z for step s+1 (hides DRAM latency behind barrier) --
        if (s + 1 < SEQ) {
            const float* z = g_Z + ((size_t)(s + 1) * BATCH + egb) * GATES + euu;
            zi = __ldcg(z);        zf = __ldcg(z + 512);
            zg = __ldcg(z + 1024); zo = __ldcg(z + 1536);
        }

        grid_barrier_h(s, leafp, rootp, flagp);
    }
}

// ---------------- kernels 3/4: y = tanh(x @ W + bias), 64x512 --------------
template<int SK, int SB>
__global__ void __launch_bounds__(256)
fc_tanh_kernel(const float* __restrict__ x, const float* __restrict__ W,
               const float* __restrict__ bias, float* __restrict__ y)
{
    int o = blockIdx.x * blockDim.x + threadIdx.x;
    int b = o >> 9, j = o & 511;
    const float* xp = x + b * SB;
    float a0 = 0.f, a1 = 0.f, a2 = 0.f, a3 = 0.f;
#pragma unroll 4
    for (int k = 0; k < HID; k += 4) {
        a0 += xp[(k + 0) * SK] * W[(size_t)(k + 0) * HID + j];
        a1 += xp[(k + 1) * SK] * W[(size_t)(k + 1) * HID + j];
        a2 += xp[(k + 2) * SK] * W[(size_t)(k + 2) * HID + j];
        a3 += xp[(k + 3) * SK] * W[(size_t)(k + 3) * HID + j];
    }
    y[o] = tanhf((a0 + a1) + (a2 + a3) + bias[j]);
}

// ---------------- kernel 5: logits = y2 @ W3 + b3 ----------------
__global__ void __launch_bounds__(128)
logits_kernel(const float* __restrict__ y, const float* __restrict__ W3,
              const float* __restrict__ b3, float* __restrict__ out)
{
    __shared__ float ys[128][68];
    const int j = blockIdx.x * 128 + threadIdx.x;

    float acc[64];
#pragma unroll
    for (int b = 0; b < 64; ++b) acc[b] = 0.0f;

    for (int kc = 0; kc < HID; kc += 128) {
        __syncthreads();
        for (int q = threadIdx.x; q < 128 * 64; q += 128) {
            int b = q >> 7, k = q & 127;
            ys[k][b] = y[b * HID + kc + k];
        }
        __syncthreads();
        if (j < VOCAB) {
#pragma unroll 4
            for (int k = 0; k < 128; ++k) {
                float w = W3[(size_t)(kc + k) * VOCAB + j];
                const float4* yr = (const float4*)&ys[k][0];
#pragma unroll
                for (int b4 = 0; b4 < 16; ++b4) {
                    float4 v = yr[b4];
                    acc[b4 * 4 + 0] += v.x * w;
                    acc[b4 * 4 + 1] += v.y * w;
                    acc[b4 * 4 + 2] += v.z * w;
                    acc[b4 * 4 + 3] += v.w * w;
                }
            }
        }
    }
    if (j < VOCAB) {
        float bb = b3[j];
#pragma unroll
        for (int b = 0; b < 64; ++b)
            out[(size_t)b * VOCAB + j] = acc[b] + bb;
    }
}

// ---------------- kernel 6: row-wise log_softmax ----------------
__global__ void __launch_bounds__(1024)
logsoftmax_kernel(const float* __restrict__ logits, float* __restrict__ out)
{
    __shared__ float red[32];
    const int b = blockIdx.x;
    const float* row  = logits + (size_t)b * VOCAB;
    float*       orow = out    + (size_t)b * VOCAB;
    const int tid = threadIdx.x;

    float m = -1e30f;
    for (int j = tid; j < VOCAB; j += 1024) m = fmaxf(m, row[j]);
#pragma unroll
    for (int o = 16; o; o >>= 1) m = fmaxf(m, __shfl_xor_sync(0xffffffffu, m, o));
    if ((tid & 31) == 0) red[tid >> 5] = m;
    __syncthreads();
    if (tid < 32) {
        float v = red[tid];
#pragma unroll
        for (int o = 16; o; o >>= 1) v = fmaxf(v, __shfl_xor_sync(0xffffffffu, v, o));
        red[tid] = v;
    }
    __syncthreads();
    m = red[0];

    float sum = 0.0f;
    for (int j = tid; j < VOCAB; j += 1024) sum += __expf(row[j] - m);
#pragma unroll
    for (int o = 16; o; o >>= 1) sum += __shfl_xor_sync(0xffffffffu, sum, o);
    __syncthreads();
    if ((tid & 31) == 0) red[tid >> 5] = sum;
    __syncthreads();
    if (tid < 32) {
        float v = red[tid];
#pragma unroll
        for (int o = 16; o; o >>= 1) v += __shfl_xor_sync(0xffffffffu, v, o);
        red[tid] = v;
    }
    __syncthreads();
    float lse = m + logf(red[0]);

    for (int j = tid; j < VOCAB; j += 1024) orow[j] = row[j] - lse;
}

// ---------------- launch ----------------
extern "C" void kernel_launch(void* const* d_in, const int* in_sizes, int n_in,
                              void* d_out, int out_size)
{
    const int*   inputs = (const int*)  d_in[0];
    const float* emb    = (const float*)d_in[1];
    const float* Wi     = (const float*)d_in[2];
    const float* Wh     = (const float*)d_in[3];
    const float* bvec   = (const float*)d_in[4];
    const float* W1     = (const float*)d_in[5];
    const float* b1     = (const float*)d_in[6];
    const float* W2     = (const float*)d_in[7];
    const float* b2     = (const float*)d_in[8];
    const float* W3     = (const float*)d_in[9];
    const float* b3     = (const float*)d_in[10];
    float* out = (float*)d_out;

    void *p_h = 0, *p_y1 = 0, *p_y2 = 0, *p_lg = 0;
    cudaGetSymbolAddress(&p_h,  g_hT);     // final h in g_hT[0], k-major [u][b]
    cudaGetSymbolAddress(&p_y1, g_y1);
    cudaGetSymbolAddress(&p_y2, g_y2);
    cudaGetSymbolAddress(&p_lg, g_logits);

    // 0. reset barrier counters (replay-safe)
    reset_kernel<<<1, 512>>>();

    // 1. Z = emb[inputs] @ Wi + b  (time-parallel)
    embed_gemm_kernel<<<dim3(GATES / 128, (SEQ * BATCH) / 128), 256>>>(inputs, emb, Wi, bvec);

    // 2. persistent LSTM recurrence
    cudaFuncSetAttribute(lstm_kernel, cudaFuncAttributeMaxDynamicSharedMemorySize, LSTM_SMEM);
    lstm_kernel<<<NBLK, 256, LSTM_SMEM>>>(Wh);

    // 3/4. dense tanh layers (fc1 reads k-major h)
    fc_tanh_kernel<64, 1><<<128, 256>>>((const float*)p_h,  W1, b1, (float*)p_y1);
    fc_tanh_kernel<1, 512><<<128, 256>>>((const float*)p_y1, W2, b2, (float*)p_y2);

    // 5. vocab projection
    logits_kernel<<<(VOCAB + 127) / 128, 128>>>((const float*)p_y2, W3, b3, (float*)p_lg);

    // 6. log_softmax
    logsoftmax_kernel<<<BATCH, 1024>>>((const float*)p_lg, out);
}

// round 10
// speedup vs baseline: 1.1574x; 1.1253x over previous
#include <cuda_runtime.h>
#include <math.h>

// ---------------- problem constants ----------------
#define BATCH   64
#define SEQ     512
#define EMB     256
#define HID     512
#define GATES   2048           // 4*HID
#define VOCAB   50257
#define NBLK    128            // persistent LSTM grid (<=148 SMs, 1 block/SM)

// ---------------- device scratch (static, no allocs) ----------------
__device__ float g_Z[(size_t)SEQ * BATCH * GATES];   // 256 MB: x@Wi + b, [s][b][4H]
__device__ float g_hT[2][HID * BATCH];               // hidden state, k-major [u][b]
__device__ float g_y1[BATCH * HID];
__device__ float g_y2[BATCH * HID];
__device__ float g_logits[(size_t)BATCH * VOCAB];
__device__ unsigned g_bar_cnt   = 0;
__device__ unsigned g_bar_sense = 0;

// ---------------- packed f32x2 helpers (FFMA2 path, sm_100+) --------------
__device__ __forceinline__ unsigned long long fma2(unsigned long long a,
                                                   unsigned long long b,
                                                   unsigned long long c)
{
    unsigned long long d;
    asm("fma.rn.f32x2 %0, %1, %2, %3;" : "=l"(d) : "l"(a), "l"(b), "l"(c));
    return d;
}
__device__ __forceinline__ unsigned long long pack2(float x)
{
    unsigned long long d;
    unsigned u = __float_as_uint(x);
    asm("mov.b64 %0, {%1, %1};" : "=l"(d) : "r"(u));
    return d;
}
__device__ __forceinline__ float lo2(unsigned long long v) { return __uint_as_float((unsigned)v); }
__device__ __forceinline__ float hi2(unsigned long long v) { return __uint_as_float((unsigned)(v >> 32)); }

// ---------------- fast activations (MUFU.TANH) ----------------
__device__ __forceinline__ float tanh_fast(float x)
{
    float y;
    asm("tanh.approx.f32 %0, %1;" : "=f"(y) : "f"(x));
    return y;
}
__device__ __forceinline__ float sigmoid_fast(float x)
{
    return 0.5f * tanh_fast(0.5f * x) + 0.5f;
}

// ---------------- cp.async helpers ----------------
__device__ __forceinline__ void cp16(unsigned dst_u32, const void* src)
{
    asm volatile("cp.async.cg.shared.global [%0], [%1], 16;"
                 :: "r"(dst_u32), "l"(src) : "memory");
}
__device__ __forceinline__ void cp_commit()
{
    asm volatile("cp.async.commit_group;" ::: "memory");
}
__device__ __forceinline__ void cp_wait0()
{
    asm volatile("cp.async.wait_group 0;" ::: "memory");
}

// ---------------- grid barrier (R7-proven: single flag, one poller) --------
__device__ __forceinline__ void grid_barrier(unsigned &sense)
{
    __syncthreads();
    if (threadIdx.x == 0) {
        sense ^= 1u;
        unsigned old;
        asm volatile("atom.add.release.gpu.global.u32 %0, [%1], %2;"
                     : "=r"(old) : "l"(&g_bar_cnt), "r"(1u) : "memory");
        if (old == NBLK - 1u) {
            asm volatile("st.global.relaxed.gpu.u32 [%0], %1;"
                         :: "l"(&g_bar_cnt), "r"(0u) : "memory");
            asm volatile("st.global.release.gpu.u32 [%0], %1;"
                         :: "l"(&g_bar_sense), "r"(sense) : "memory");
        } else {
            unsigned v;
            do {
                asm volatile("ld.global.acquire.gpu.u32 %0, [%1];"
                             : "=r"(v) : "l"(&g_bar_sense) : "memory");
            } while (v != sense);
        }
    }
    __syncthreads();
}

// ---------------- kernel 1: Z = gather(emb, inputs) @ Wi + b --------------
// (R2-proven, unchanged) 128x128 tile, K-chunks of 16, 8x8 thread tile, f32x2.
__global__ void __launch_bounds__(256, 2)
embed_gemm_kernel(const int* __restrict__ inputs, const float* __restrict__ emb,
                  const float* __restrict__ Wi, const float* __restrict__ bias)
{
    __shared__ float As[128][17];
    __shared__ float Bs[16][132];

    const int t  = threadIdx.x;
    const int mt = blockIdx.y;
    const int nt = blockIdx.x;
    const int tx = t & 15;
    const int ty = t >> 4;

    const int ra   = t >> 1;
    const int koff = (t & 1) * 8;
    const int rowg = mt * 128 + ra;
    const int s    = rowg >> 6;
    const int b    = rowg & 63;
    const float* erow = emb + (size_t)inputs[b * SEQ + s] * EMB;

    const int bkr  = t >> 4;
    const int bcol = (t & 15) * 8;

    unsigned long long acc[8][4];
#pragma unroll
    for (int i = 0; i < 8; ++i)
#pragma unroll
        for (int j = 0; j < 4; ++j) acc[i][j] = 0ULL;

    for (int k0 = 0; k0 < EMB; k0 += 16) {
        {
            float4 a0 = *(const float4*)(erow + k0 + koff);
            float4 a1 = *(const float4*)(erow + k0 + koff + 4);
            As[ra][koff + 0] = a0.x; As[ra][koff + 1] = a0.y;
            As[ra][koff + 2] = a0.z; As[ra][koff + 3] = a0.w;
            As[ra][koff + 4] = a1.x; As[ra][koff + 5] = a1.y;
            As[ra][koff + 6] = a1.z; As[ra][koff + 7] = a1.w;
        }
        {
            const float* wsrc = Wi + (size_t)(k0 + bkr) * GATES + nt * 128 + bcol;
            float4 b0v = *(const float4*)(wsrc);
            float4 b1v = *(const float4*)(wsrc + 4);
            *(float4*)&Bs[bkr][bcol]     = b0v;
            *(float4*)&Bs[bkr][bcol + 4] = b1v;
        }
        __syncthreads();

#pragma unroll
        for (int k = 0; k < 16; ++k) {
            unsigned long long pa[8];
#pragma unroll
            for (int i = 0; i < 4; ++i) {
                pa[i]     = pack2(As[ty * 4 + i][k]);
                pa[i + 4] = pack2(As[64 + ty * 4 + i][k]);
            }
            ulonglong2 b0v = *(const ulonglong2*)&Bs[k][tx * 4];
            ulonglong2 b1v = *(const ulonglong2*)&Bs[k][64 + tx * 4];
#pragma unroll
            for (int i = 0; i < 8; ++i) {
                acc[i][0] = fma2(pa[i], b0v.x, acc[i][0]);
                acc[i][1] = fma2(pa[i], b0v.y, acc[i][1]);
                acc[i][2] = fma2(pa[i], b1v.x, acc[i][2]);
                acc[i][3] = fma2(pa[i], b1v.y, acc[i][3]);
            }
        }
        __syncthreads();
    }

    float4 bb0 = *(const float4*)(bias + nt * 128 + tx * 4);
    float4 bb1 = *(const float4*)(bias + nt * 128 + 64 + tx * 4);
#pragma unroll
    for (int i = 0; i < 8; ++i) {
        int row = mt * 128 + ((i < 4) ? (ty * 4 + i) : (64 + ty * 4 + i - 4));
        float* zr = g_Z + (size_t)row * GATES + nt * 128;
        float4 v0, v1;
        v0.x = lo2(acc[i][0]) + bb0.x; v0.y = hi2(acc[i][0]) + bb0.y;
        v0.z = lo2(acc[i][1]) + bb0.z; v0.w = hi2(acc[i][1]) + bb0.w;
        v1.x = lo2(acc[i][2]) + bb1.x; v1.y = hi2(acc[i][2]) + bb1.y;
        v1.z = lo2(acc[i][3]) + bb1.z; v1.w = hi2(acc[i][3]) + bb1.w;
        *(float4*)(zr + tx * 4)      = v0;
        *(float4*)(zr + 64 + tx * 4) = v1;
    }
}

// ---------------- kernel 2: persistent LSTM over 512 steps ----------------
// (R7-proven core) 128 blocks = 64 unit-groups x 2 batch-halves; block =
// 8 units x 32 batches; 256 threads = 8 warps; WARP = one kc strip (k fixed
// per iteration -> all LDS broadcast, conflict-free).
// NEW vs R7: warp-private staging. Warp kc's mainloop reads ONLY its own 8KB
// h strip, so each warp stages its own strip (16 cp16/lane), waits its own
// cp group, __syncwarp, and computes immediately -- no block-wide sync, and
// the chip-wide 1300-cyc LTS staging bill overlaps compute across warps.
#define LSTM_SMEM (65536 + 65536 + 36864)

__global__ void __launch_bounds__(256, 1)
lstm_kernel(const float* __restrict__ Wh)
{
    extern __shared__ float sm[];
    float4*     h_s4 = (float4*)sm;                           // [512][8] (64KB)
    ulonglong2* Whs  = (ulonglong2*)((char*)sm + 65536);      // [512][8] (64KB)
    ulonglong2* red  = (ulonglong2*)((char*)sm + 131072);     // [256 p][9] skew

    const int tid  = threadIdx.x;
    const int kc   = tid >> 5;           // warp id = k-strip 0..7
    const int lane = tid & 31;
    const int up   = (tid >> 3) & 3;     // unit pair 0..3 (units 2up, 2up+1)
    const int bg   = tid & 7;            // batch group 0..7 (4 batches)
    const int ub   = blockIdx.x >> 1;    // unit group 0..63
    const int bh   = blockIdx.x & 1;     // batch half
    const unsigned h_s_u32 = (unsigned)__cvta_generic_to_shared(h_s4);

    // epilogue ownership: pair p = tid -> unit eu, local batch ebl
    const int eu  = tid >> 5;            // 0..7
    const int ebl = tid & 31;            // 0..31
    const int euu = ub * 8 + eu;
    const int egb = bh * 32 + ebl;

    // stage Wh slice once: Whs[k*8+u] = {(wi,wf),(wg,wo)} for col = ub*8+u
    for (int i = tid; i < HID * 8; i += 256) {
        int k = i >> 3, u2 = i & 7;
        const float* w = Wh + (size_t)k * GATES + ub * 8 + u2;
        float4 v = make_float4(w[0], w[512], w[1024], w[1536]);
        Whs[i] = *(ulonglong2*)&v;
    }

    float c = 0.0f;                      // cell state of pair p = tid
    unsigned sense = 0;
    __syncthreads();

    const ulonglong2* wp = Whs  + kc * 512 + up * 2;   // iter i: wp[i*8], wp[i*8+1]
    const float4*     hp = h_s4 + kc * 512 + bg;       // iter i: hp[i*8]

    // this warp's staging base: chunks [kc*512, kc*512+512), 16 per lane
    const int cbase = kc * 512 + lane;

    // Z prefetch for step 0 (gates for pair p)
    const float* z0 = g_Z + (size_t)egb * GATES + euu;
    float zi = __ldcg(z0), zf = __ldcg(z0 + 512);
    float zg = __ldcg(z0 + 1024), zo = __ldcg(z0 + 1536);

    for (int s = 0; s < SEQ; ++s) {
        unsigned long long aif[2][4] = {{0,0,0,0},{0,0,0,0}};
        unsigned long long ago[2][4] = {{0,0,0,0},{0,0,0,0}};

        if (s > 0) {
            // ---- warp-private staging of this warp's h strip (8KB) ----
            const float4* src4 = (const float4*)g_hT[s & 1];
#pragma unroll
            for (int j = 0; j < 16; ++j) {
                int chunk = cbase + j * 32;                // within own strip
                cp16(h_s_u32 + chunk * 16,
                     src4 + (chunk >> 3) * 16 + bh * 8 + (chunk & 7));
            }
            cp_commit();
            cp_wait0();        // own 16 copies landed (and visible block-wide)
            __syncwarp();      // all 32 lanes' copies done -> strip complete

            // ---- mainloop: k fixed per iteration, all LDS broadcast ----
#pragma unroll 4
            for (int i = 0; i < 64; ++i) {
                ulonglong2 w0 = wp[i * 8];       // unit 2up   (wi,wf),(wg,wo)
                ulonglong2 w1 = wp[i * 8 + 1];   // unit 2up+1
                float4     hv = hp[i * 8];       // 4 batches
                unsigned long long p;
                p = pack2(hv.x);
                aif[0][0] = fma2(p, w0.x, aif[0][0]); ago[0][0] = fma2(p, w0.y, ago[0][0]);
                aif[1][0] = fma2(p, w1.x, aif[1][0]); ago[1][0] = fma2(p, w1.y, ago[1][0]);
                p = pack2(hv.y);
                aif[0][1] = fma2(p, w0.x, aif[0][1]); ago[0][1] = fma2(p, w0.y, ago[0][1]);
                aif[1][1] = fma2(p, w1.x, aif[1][1]); ago[1][1] = fma2(p, w1.y, ago[1][1]);
                p = pack2(hv.z);
                aif[0][2] = fma2(p, w0.x, aif[0][2]); ago[0][2] = fma2(p, w0.y, ago[0][2]);
                aif[1][2] = fma2(p, w1.x, aif[1][2]); ago[1][2] = fma2(p, w1.y, ago[1][2]);
                p = pack2(hv.w);
                aif[0][3] = fma2(p, w0.x, aif[0][3]); ago[0][3] = fma2(p, w0.y, ago[0][3]);
                aif[1][3] = fma2(p, w1.x, aif[1][3]); ago[1][3] = fma2(p, w1.y, ago[1][3]);
            }
        }

        // ---- write partials to skewed red[p*9 + kc] ----
#pragma unroll
        for (int uo = 0; uo < 2; ++uo)
#pragma unroll
            for (int bi = 0; bi < 4; ++bi) {
                int p = (2 * up + uo) * 32 + bg * 4 + bi;
                red[p * 9 + kc] = make_ulonglong2(aif[uo][bi], ago[uo][bi]);
            }
        __syncthreads();

        // ---- reduce 8 kc partials for pair p = tid; epilogue ----
        {
            float fi = zi, ff = zf, fg_ = zg, fo = zo;
#pragma unroll
            for (int k8 = 0; k8 < 8; ++k8) {
                ulonglong2 v = red[tid * 9 + k8];
                fi += lo2(v.x); ff += hi2(v.x);
                fg_ += lo2(v.y); fo += hi2(v.y);
            }
            float ig  = sigmoid_fast(fi);
            float fg2 = sigmoid_fast(ff);
            float gg  = tanh_fast(fg_);
            float og  = sigmoid_fast(fo);
            c = fg2 * c + ig * gg;
            float hv = og * tanh_fast(c);
            g_hT[(s + 1) & 1][euu * 64 + egb] = hv;    // final h in g_hT[0]
        }

        // ---- prefetch Z for step s+1 (hides DRAM latency behind barrier) --
        if (s + 1 < SEQ) {
            const float* z = g_Z + ((size_t)(s + 1) * BATCH + egb) * GATES + euu;
            zi = __ldcg(z);        zf = __ldcg(z + 512);
            zg = __ldcg(z + 1024); zo = __ldcg(z + 1536);
        }

        grid_barrier(sense);
    }
}

// ---------------- kernels 3/4: y = tanh(x @ W + bias), 64x512 --------------
template<int SK, int SB>
__global__ void __launch_bounds__(256)
fc_tanh_kernel(const float* __restrict__ x, const float* __restrict__ W,
               const float* __restrict__ bias, float* __restrict__ y)
{
    int o = blockIdx.x * blockDim.x + threadIdx.x;
    int b = o >> 9, j = o & 511;
    const float* xp = x + b * SB;
    float a0 = 0.f, a1 = 0.f, a2 = 0.f, a3 = 0.f;
#pragma unroll 4
    for (int k = 0; k < HID; k += 4) {
        a0 += xp[(k + 0) * SK] * W[(size_t)(k + 0) * HID + j];
        a1 += xp[(k + 1) * SK] * W[(size_t)(k + 1) * HID + j];
        a2 += xp[(k + 2) * SK] * W[(size_t)(k + 2) * HID + j];
        a3 += xp[(k + 3) * SK] * W[(size_t)(k + 3) * HID + j];
    }
    y[o] = tanhf((a0 + a1) + (a2 + a3) + bias[j]);
}

// ---------------- kernel 5: logits = y2 @ W3 + b3 ----------------
__global__ void __launch_bounds__(128)
logits_kernel(const float* __restrict__ y, const float* __restrict__ W3,
              const float* __restrict__ b3, float* __restrict__ out)
{
    __shared__ float ys[128][68];
    const int j = blockIdx.x * 128 + threadIdx.x;

    float acc[64];
#pragma unroll
    for (int b = 0; b < 64; ++b) acc[b] = 0.0f;

    for (int kc = 0; kc < HID; kc += 128) {
        __syncthreads();
        for (int q = threadIdx.x; q < 128 * 64; q += 128) {
            int b = q >> 7, k = q & 127;
            ys[k][b] = y[b * HID + kc + k];
        }
        __syncthreads();
        if (j < VOCAB) {
#pragma unroll 4
            for (int k = 0; k < 128; ++k) {
                float w = W3[(size_t)(kc + k) * VOCAB + j];
                const float4* yr = (const float4*)&ys[k][0];
#pragma unroll
                for (int b4 = 0; b4 < 16; ++b4) {
                    float4 v = yr[b4];
                    acc[b4 * 4 + 0] += v.x * w;
                    acc[b4 * 4 + 1] += v.y * w;
                    acc[b4 * 4 + 2] += v.z * w;
                    acc[b4 * 4 + 3] += v.w * w;
                }
            }
        }
    }
    if (j < VOCAB) {
        float bb = b3[j];
#pragma unroll
        for (int b = 0; b < 64; ++b)
            out[(size_t)b * VOCAB + j] = acc[b] + bb;
    }
}

// ---------------- kernel 6: row-wise log_softmax ----------------
__global__ void __launch_bounds__(1024)
logsoftmax_kernel(const float* __restrict__ logits, float* __restrict__ out)
{
    __shared__ float red[32];
    const int b = blockIdx.x;
    const float* row  = logits + (size_t)b * VOCAB;
    float*       orow = out    + (size_t)b * VOCAB;
    const int tid = threadIdx.x;

    float m = -1e30f;
    for (int j = tid; j < VOCAB; j += 1024) m = fmaxf(m, row[j]);
#pragma unroll
    for (int o = 16; o; o >>= 1) m = fmaxf(m, __shfl_xor_sync(0xffffffffu, m, o));
    if ((tid & 31) == 0) red[tid >> 5] = m;
    __syncthreads();
    if (tid < 32) {
        float v = red[tid];
#pragma unroll
        for (int o = 16; o; o >>= 1) v = fmaxf(v, __shfl_xor_sync(0xffffffffu, v, o));
        red[tid] = v;
    }
    __syncthreads();
    m = red[0];

    float sum = 0.0f;
    for (int j = tid; j < VOCAB; j += 1024) sum += __expf(row[j] - m);
#pragma unroll
    for (int o = 16; o; o >>= 1) sum += __shfl_xor_sync(0xffffffffu, sum, o);
    __syncthreads();
    if ((tid & 31) == 0) red[tid >> 5] = sum;
    __syncthreads();
    if (tid < 32) {
        float v = red[tid];
#pragma unroll
        for (int o = 16; o; o >>= 1) v += __shfl_xor_sync(0xffffffffu, v, o);
        red[tid] = v;
    }
    __syncthreads();
    float lse = m + logf(red[0]);

    for (int j = tid; j < VOCAB; j += 1024) orow[j] = row[j] - lse;
}

// ---------------- launch ----------------
extern "C" void kernel_launch(void* const* d_in, const int* in_sizes, int n_in,
                              void* d_out, int out_size)
{
    const int*   inputs = (const int*)  d_in[0];
    const float* emb    = (const float*)d_in[1];
    const float* Wi     = (const float*)d_in[2];
    const float* Wh     = (const float*)d_in[3];
    const float* bvec   = (const float*)d_in[4];
    const float* W1     = (const float*)d_in[5];
    const float* b1     = (const float*)d_in[6];
    const float* W2     = (const float*)d_in[7];
    const float* b2     = (const float*)d_in[8];
    const float* W3     = (const float*)d_in[9];
    const float* b3     = (const float*)d_in[10];
    float* out = (float*)d_out;

    void *p_h = 0, *p_y1 = 0, *p_y2 = 0, *p_lg = 0;
    cudaGetSymbolAddress(&p_h,  g_hT);     // final h in g_hT[0], k-major [u][b]
    cudaGetSymbolAddress(&p_y1, g_y1);
    cudaGetSymbolAddress(&p_y2, g_y2);
    cudaGetSymbolAddress(&p_lg, g_logits);

    // 1. Z = emb[inputs] @ Wi + b  (time-parallel)
    embed_gemm_kernel<<<dim3(GATES / 128, (SEQ * BATCH) / 128), 256>>>(inputs, emb, Wi, bvec);

    // 2. persistent LSTM recurrence
    cudaFuncSetAttribute(lstm_kernel, cudaFuncAttributeMaxDynamicSharedMemorySize, LSTM_SMEM);
    lstm_kernel<<<NBLK, 256, LSTM_SMEM>>>(Wh);

    // 3/4. dense tanh layers (fc1 reads k-major h)
    fc_tanh_kernel<64, 1><<<128, 256>>>((const float*)p_h,  W1, b1, (float*)p_y1);
    fc_tanh_kernel<1, 512><<<128, 256>>>((const float*)p_y1, W2, b2, (float*)p_y2);

    // 5. vocab projection
    logits_kernel<<<(VOCAB + 127) / 128, 128>>>((const float*)p_y2, W3, b3, (float*)p_lg);

    // 6. log_softmax
    logsoftmax_kernel<<<BATCH, 1024>>>((const float*)p_lg, out);
}

// round 11
// speedup vs baseline: 1.1982x; 1.0353x over previous
#include <cuda_runtime.h>
#include <math.h>

// ---------------- problem constants ----------------
#define BATCH   64
#define SEQ     512
#define EMB     256
#define HID     512
#define GATES   2048           // 4*HID
#define VOCAB   50257
#define NBLK    128            // persistent LSTM grid (<=148 SMs, 1 block/SM)

// ---------------- device scratch (static, no allocs) ----------------
__device__ float g_Z[(size_t)SEQ * BATCH * GATES];   // 256 MB: x@Wi + b, [s][b][4H]
__device__ float g_hT[2][HID * BATCH];               // hidden state, k-major [u][b]
__device__ float g_y1[BATCH * HID];
__device__ float g_y2[BATCH * HID];
__device__ float g_logits[(size_t)BATCH * VOCAB];
// 4 independent batch-quarter barriers, each on its own 128B line.
// Sense-reversing: after 512 steps (even) state returns to 0 -> replay-safe.
__device__ unsigned g_bar_cnt4[4 * 32];
__device__ unsigned g_bar_sense4[4 * 32];

// ---------------- packed f32x2 helpers (FFMA2 path, sm_100+) --------------
__device__ __forceinline__ unsigned long long fma2(unsigned long long a,
                                                   unsigned long long b,
                                                   unsigned long long c)
{
    unsigned long long d;
    asm("fma.rn.f32x2 %0, %1, %2, %3;" : "=l"(d) : "l"(a), "l"(b), "l"(c));
    return d;
}
__device__ __forceinline__ unsigned long long pack2(float x)
{
    unsigned long long d;
    unsigned u = __float_as_uint(x);
    asm("mov.b64 %0, {%1, %1};" : "=l"(d) : "r"(u));
    return d;
}
__device__ __forceinline__ float lo2(unsigned long long v) { return __uint_as_float((unsigned)v); }
__device__ __forceinline__ float hi2(unsigned long long v) { return __uint_as_float((unsigned)(v >> 32)); }

// ---------------- fast activations (MUFU.TANH) ----------------
__device__ __forceinline__ float tanh_fast(float x)
{
    float y;
    asm("tanh.approx.f32 %0, %1;" : "=f"(y) : "f"(x));
    return y;
}
__device__ __forceinline__ float sigmoid_fast(float x)
{
    return 0.5f * tanh_fast(0.5f * x) + 0.5f;
}

// ---------------- cp.async helpers ----------------
__device__ __forceinline__ void cp16(unsigned dst_u32, const void* src)
{
    asm volatile("cp.async.cg.shared.global [%0], [%1], 16;"
                 :: "r"(dst_u32), "l"(src) : "memory");
}
__device__ __forceinline__ void cp_commit()
{
    asm volatile("cp.async.commit_group;" ::: "memory");
}
__device__ __forceinline__ void cp_wait0()
{
    asm volatile("cp.async.wait_group 0;" ::: "memory");
}

// ---------------- group grid barrier (R7 pattern, n arrivals) --------------
__device__ __forceinline__ void grid_barrier_g(unsigned &sense, unsigned* cnt,
                                               unsigned* flag, unsigned n)
{
    __syncthreads();
    if (threadIdx.x == 0) {
        sense ^= 1u;
        unsigned old;
        asm volatile("atom.add.release.gpu.global.u32 %0, [%1], %2;"
                     : "=r"(old) : "l"(cnt), "r"(1u) : "memory");
        if (old == n - 1u) {
            asm volatile("st.global.relaxed.gpu.u32 [%0], %1;"
                         :: "l"(cnt), "r"(0u) : "memory");
            asm volatile("st.global.release.gpu.u32 [%0], %1;"
                         :: "l"(flag), "r"(sense) : "memory");
        } else {
            unsigned v;
            do {
                asm volatile("ld.global.acquire.gpu.u32 %0, [%1];"
                             : "=r"(v) : "l"(flag) : "memory");
            } while (v != sense);
        }
    }
    __syncthreads();
}

// ---------------- kernel 1: Z = gather(emb, inputs) @ Wi + b --------------
// (R2-proven, unchanged) 128x128 tile, K-chunks of 16, 8x8 thread tile, f32x2.
__global__ void __launch_bounds__(256, 2)
embed_gemm_kernel(const int* __restrict__ inputs, const float* __restrict__ emb,
                  const float* __restrict__ Wi, const float* __restrict__ bias)
{
    __shared__ float As[128][17];
    __shared__ float Bs[16][132];

    const int t  = threadIdx.x;
    const int mt = blockIdx.y;
    const int nt = blockIdx.x;
    const int tx = t & 15;
    const int ty = t >> 4;

    const int ra   = t >> 1;
    const int koff = (t & 1) * 8;
    const int rowg = mt * 128 + ra;
    const int s    = rowg >> 6;
    const int b    = rowg & 63;
    const float* erow = emb + (size_t)inputs[b * SEQ + s] * EMB;

    const int bkr  = t >> 4;
    const int bcol = (t & 15) * 8;

    unsigned long long acc[8][4];
#pragma unroll
    for (int i = 0; i < 8; ++i)
#pragma unroll
        for (int j = 0; j < 4; ++j) acc[i][j] = 0ULL;

    for (int k0 = 0; k0 < EMB; k0 += 16) {
        {
            float4 a0 = *(const float4*)(erow + k0 + koff);
            float4 a1 = *(const float4*)(erow + k0 + koff + 4);
            As[ra][koff + 0] = a0.x; As[ra][koff + 1] = a0.y;
            As[ra][koff + 2] = a0.z; As[ra][koff + 3] = a0.w;
            As[ra][koff + 4] = a1.x; As[ra][koff + 5] = a1.y;
            As[ra][koff + 6] = a1.z; As[ra][koff + 7] = a1.w;
        }
        {
            const float* wsrc = Wi + (size_t)(k0 + bkr) * GATES + nt * 128 + bcol;
            float4 b0v = *(const float4*)(wsrc);
            float4 b1v = *(const float4*)(wsrc + 4);
            *(float4*)&Bs[bkr][bcol]     = b0v;
            *(float4*)&Bs[bkr][bcol + 4] = b1v;
        }
        __syncthreads();

#pragma unroll
        for (int k = 0; k < 16; ++k) {
            unsigned long long pa[8];
#pragma unroll
            for (int i = 0; i < 4; ++i) {
                pa[i]     = pack2(As[ty * 4 + i][k]);
                pa[i + 4] = pack2(As[64 + ty * 4 + i][k]);
            }
            ulonglong2 b0v = *(const ulonglong2*)&Bs[k][tx * 4];
            ulonglong2 b1v = *(const ulonglong2*)&Bs[k][64 + tx * 4];
#pragma unroll
            for (int i = 0; i < 8; ++i) {
                acc[i][0] = fma2(pa[i], b0v.x, acc[i][0]);
                acc[i][1] = fma2(pa[i], b0v.y, acc[i][1]);
                acc[i][2] = fma2(pa[i], b1v.x, acc[i][2]);
                acc[i][3] = fma2(pa[i], b1v.y, acc[i][3]);
            }
        }
        __syncthreads();
    }

    float4 bb0 = *(const float4*)(bias + nt * 128 + tx * 4);
    float4 bb1 = *(const float4*)(bias + nt * 128 + 64 + tx * 4);
#pragma unroll
    for (int i = 0; i < 8; ++i) {
        int row = mt * 128 + ((i < 4) ? (ty * 4 + i) : (64 + ty * 4 + i - 4));
        float* zr = g_Z + (size_t)row * GATES + nt * 128;
        float4 v0, v1;
        v0.x = lo2(acc[i][0]) + bb0.x; v0.y = hi2(acc[i][0]) + bb0.y;
        v0.z = lo2(acc[i][1]) + bb0.z; v0.w = hi2(acc[i][1]) + bb0.w;
        v1.x = lo2(acc[i][2]) + bb1.x; v1.y = hi2(acc[i][2]) + bb1.y;
        v1.z = lo2(acc[i][3]) + bb1.z; v1.w = hi2(acc[i][3]) + bb1.w;
        *(float4*)(zr + tx * 4)      = v0;
        *(float4*)(zr + 64 + tx * 4) = v1;
    }
}

// ---------------- kernel 2: persistent LSTM over 512 steps ----------------
// 128 blocks = 32 unit-groups x 4 BATCH-QUARTERS; block = 16 units x 16
// batches. Batch quarters are fully independent -> 4 separate 32-block
// barriers; chip staging traffic halves to 4MB/step (32KB/block).
// 256 threads = 8 warps; WARP = one kc strip of 64 k (k fixed per inner
// iteration -> all LDS broadcast/conflict-free; R7/R10-proven pattern).
// Lanes = (up 0..7) x (bg 0..3); thread tile = 2 units x 4 batches.
// smem: h_s4 [512k][4bg] f4 (32KB) + Whs [512k][16u] ull2 (128KB) +
//       red [256p][9] ull2 (36KB) = 196KB.
#define LSTM_SMEM (32768 + 131072 + 36864)

__global__ void __launch_bounds__(256, 1)
lstm_kernel(const float* __restrict__ Wh)
{
    extern __shared__ float sm[];
    float4*     h_s4 = (float4*)sm;                           // [512][4]
    ulonglong2* Whs  = (ulonglong2*)((char*)sm + 32768);      // [512][16]
    ulonglong2* red  = (ulonglong2*)((char*)sm + 163840);     // [256 p][9]

    const int tid  = threadIdx.x;
    const int kc   = tid >> 5;           // warp id = k-strip 0..7 (64 k each)
    const int lane = tid & 31;
    const int up   = lane >> 2;          // unit pair 0..7 (units 2up, 2up+1)
    const int bg   = lane & 3;           // batch group 0..3 (4 batches)
    const int ub   = blockIdx.x >> 2;    // unit group 0..31 (16 units)
    const int q    = blockIdx.x & 3;     // batch quarter 0..3 (16 batches)
    const unsigned h_s_u32 = (unsigned)__cvta_generic_to_shared(h_s4);

    unsigned* cntp  = &g_bar_cnt4[q * 32];
    unsigned* snsp  = &g_bar_sense4[q * 32];

    // epilogue ownership: pair p = tid -> unit u_local, batch b_local
    const int eul = tid >> 4;            // 0..15
    const int ebl = tid & 15;            // 0..15
    const int euu = ub * 16 + eul;       // global unit
    const int egb = q * 16 + ebl;        // global batch

    // stage Wh slice once: Whs[k*16+u] = {(wi,wf),(wg,wo)} for col = ub*16+u
    for (int i = tid; i < HID * 16; i += 256) {
        int k = i >> 4, u2 = i & 15;
        const float* w = Wh + (size_t)k * GATES + ub * 16 + u2;
        float4 v = make_float4(w[0], w[512], w[1024], w[1536]);
        Whs[i] = *(ulonglong2*)&v;
    }

    float c = 0.0f;                      // cell state of pair p = tid
    unsigned sense = 0;
    __syncthreads();

    const ulonglong2* wp = Whs  + kc * 1024 + up * 2;  // iter i: wp[i*16], +1
    const float4*     hp = h_s4 + kc * 256 + bg;       // iter i: hp[i*4]

    // warp-private staging: warp kc owns f4-chunks [kc*256, kc*256+256)
    const int cbase = kc * 256 + lane;                 // 8 chunks per lane

    // Z prefetch for step 0 (gates for pair p)
    const float* z0 = g_Z + (size_t)egb * GATES + euu;
    float zi = __ldcg(z0), zf = __ldcg(z0 + 512);
    float zg = __ldcg(z0 + 1024), zo = __ldcg(z0 + 1536);

    for (int s = 0; s < SEQ; ++s) {
        unsigned long long aif[2][4] = {{0,0,0,0},{0,0,0,0}};
        unsigned long long ago[2][4] = {{0,0,0,0},{0,0,0,0}};

        if (s > 0) {
            // ---- warp-private staging of this warp's h strip (4KB) ----
            const float4* src4 = (const float4*)g_hT[s & 1];
#pragma unroll
            for (int j = 0; j < 8; ++j) {
                int chunk = cbase + j * 32;             // within own strip
                int k = chunk >> 2, cc = chunk & 3;
                cp16(h_s_u32 + chunk * 16, src4 + k * 16 + q * 4 + cc);
            }
            cp_commit();
            cp_wait0();        // own 8 copies landed
            __syncwarp();      // all 32 lanes done -> strip complete

            // ---- mainloop: k fixed per iteration, all LDS broadcast ----
#pragma unroll 4
            for (int i = 0; i < 64; ++i) {
                ulonglong2 w0 = wp[i * 16];      // unit 2up   (wi,wf),(wg,wo)
                ulonglong2 w1 = wp[i * 16 + 1];  // unit 2up+1
                float4     hv = hp[i * 4];       // 4 batches
                unsigned long long p;
                p = pack2(hv.x);
                aif[0][0] = fma2(p, w0.x, aif[0][0]); ago[0][0] = fma2(p, w0.y, ago[0][0]);
                aif[1][0] = fma2(p, w1.x, aif[1][0]); ago[1][0] = fma2(p, w1.y, ago[1][0]);
                p = pack2(hv.y);
                aif[0][1] = fma2(p, w0.x, aif[0][1]); ago[0][1] = fma2(p, w0.y, ago[0][1]);
                aif[1][1] = fma2(p, w1.x, aif[1][1]); ago[1][1] = fma2(p, w1.y, ago[1][1]);
                p = pack2(hv.z);
                aif[0][2] = fma2(p, w0.x, aif[0][2]); ago[0][2] = fma2(p, w0.y, ago[0][2]);
                aif[1][2] = fma2(p, w1.x, aif[1][2]); ago[1][2] = fma2(p, w1.y, ago[1][2]);
                p = pack2(hv.w);
                aif[0][3] = fma2(p, w0.x, aif[0][3]); ago[0][3] = fma2(p, w0.y, ago[0][3]);
                aif[1][3] = fma2(p, w1.x, aif[1][3]); ago[1][3] = fma2(p, w1.y, ago[1][3]);
            }
        }

        // ---- write partials to skewed red[p*9 + kc] ----
#pragma unroll
        for (int uo = 0; uo < 2; ++uo)
#pragma unroll
            for (int bi = 0; bi < 4; ++bi) {
                int p = (2 * up + uo) * 16 + bg * 4 + bi;
                red[p * 9 + kc] = make_ulonglong2(aif[uo][bi], ago[uo][bi]);
            }
        __syncthreads();

        // ---- reduce 8 kc partials for pair p = tid; epilogue ----
        {
            float fi = zi, ff = zf, fg_ = zg, fo = zo;
#pragma unroll
            for (int k8 = 0; k8 < 8; ++k8) {
                ulonglong2 v = red[tid * 9 + k8];
                fi += lo2(v.x); ff += hi2(v.x);
                fg_ += lo2(v.y); fo += hi2(v.y);
            }
            float ig  = sigmoid_fast(fi);
            float fg2 = sigmoid_fast(ff);
            float gg  = tanh_fast(fg_);
            float og  = sigmoid_fast(fo);
            c = fg2 * c + ig * gg;
            float hv = og * tanh_fast(c);
            g_hT[(s + 1) & 1][euu * 64 + egb] = hv;    // final h in g_hT[0]
        }

        // ---- prefetch Z for step s+1 (hides DRAM latency behind barrier) --
        if (s + 1 < SEQ) {
            const float* z = g_Z + ((size_t)(s + 1) * BATCH + egb) * GATES + euu;
            zi = __ldcg(z);        zf = __ldcg(z + 512);
            zg = __ldcg(z + 1024); zo = __ldcg(z + 1536);
        }

        grid_barrier_g(sense, cntp, snsp, 32u);   // only this batch quarter
    }
}

// ---------------- kernels 3/4: y = tanh(x @ W + bias), 64x512 --------------
template<int SK, int SB>
__global__ void __launch_bounds__(256)
fc_tanh_kernel(const float* __restrict__ x, const float* __restrict__ W,
               const float* __restrict__ bias, float* __restrict__ y)
{
    int o = blockIdx.x * blockDim.x + threadIdx.x;
    int b = o >> 9, j = o & 511;
    const float* xp = x + b * SB;
    float a0 = 0.f, a1 = 0.f, a2 = 0.f, a3 = 0.f;
#pragma unroll 4
    for (int k = 0; k < HID; k += 4) {
        a0 += xp[(k + 0) * SK] * W[(size_t)(k + 0) * HID + j];
        a1 += xp[(k + 1) * SK] * W[(size_t)(k + 1) * HID + j];
        a2 += xp[(k + 2) * SK] * W[(size_t)(k + 2) * HID + j];
        a3 += xp[(k + 3) * SK] * W[(size_t)(k + 3) * HID + j];
    }
    y[o] = tanhf((a0 + a1) + (a2 + a3) + bias[j]);
}

// ---------------- kernel 5: logits = y2 @ W3 + b3 ----------------
__global__ void __launch_bounds__(128)
logits_kernel(const float* __restrict__ y, const float* __restrict__ W3,
              const float* __restrict__ b3, float* __restrict__ out)
{
    __shared__ float ys[128][68];
    const int j = blockIdx.x * 128 + threadIdx.x;

    float acc[64];
#pragma unroll
    for (int b = 0; b < 64; ++b) acc[b] = 0.0f;

    for (int kc = 0; kc < HID; kc += 128) {
        __syncthreads();
        for (int q = threadIdx.x; q < 128 * 64; q += 128) {
            int b = q >> 7, k = q & 127;
            ys[k][b] = y[b * HID + kc + k];
        }
        __syncthreads();
        if (j < VOCAB) {
#pragma unroll 4
            for (int k = 0; k < 128; ++k) {
                float w = W3[(size_t)(kc + k) * VOCAB + j];
                const float4* yr = (const float4*)&ys[k][0];
#pragma unroll
                for (int b4 = 0; b4 < 16; ++b4) {
                    float4 v = yr[b4];
                    acc[b4 * 4 + 0] += v.x * w;
                    acc[b4 * 4 + 1] += v.y * w;
                    acc[b4 * 4 + 2] += v.z * w;
                    acc[b4 * 4 + 3] += v.w * w;
                }
            }
        }
    }
    if (j < VOCAB) {
        float bb = b3[j];
#pragma unroll
        for (int b = 0; b < 64; ++b)
            out[(size_t)b * VOCAB + j] = acc[b] + bb;
    }
}

// ---------------- kernel 6: row-wise log_softmax ----------------
__global__ void __launch_bounds__(1024)
logsoftmax_kernel(const float* __restrict__ logits, float* __restrict__ out)
{
    __shared__ float red[32];
    const int b = blockIdx.x;
    const float* row  = logits + (size_t)b * VOCAB;
    float*       orow = out    + (size_t)b * VOCAB;
    const int tid = threadIdx.x;

    float m = -1e30f;
    for (int j = tid; j < VOCAB; j += 1024) m = fmaxf(m, row[j]);
#pragma unroll
    for (int o = 16; o; o >>= 1) m = fmaxf(m, __shfl_xor_sync(0xffffffffu, m, o));
    if ((tid & 31) == 0) red[tid >> 5] = m;
    __syncthreads();
    if (tid < 32) {
        float v = red[tid];
#pragma unroll
        for (int o = 16; o; o >>= 1) v = fmaxf(v, __shfl_xor_sync(0xffffffffu, v, o));
        red[tid] = v;
    }
    __syncthreads();
    m = red[0];

    float sum = 0.0f;
    for (int j = tid; j < VOCAB; j += 1024) sum += __expf(row[j] - m);
#pragma unroll
    for (int o = 16; o; o >>= 1) sum += __shfl_xor_sync(0xffffffffu, sum, o);
    __syncthreads();
    if ((tid & 31) == 0) red[tid >> 5] = sum;
    __syncthreads();
    if (tid < 32) {
        float v = red[tid];
#pragma unroll
        for (int o = 16; o; o >>= 1) v += __shfl_xor_sync(0xffffffffu, v, o);
        red[tid] = v;
    }
    __syncthreads();
    float lse = m + logf(red[0]);

    for (int j = tid; j < VOCAB; j += 1024) orow[j] = row[j] - lse;
}

// ---------------- launch ----------------
extern "C" void kernel_launch(void* const* d_in, const int* in_sizes, int n_in,
                              void* d_out, int out_size)
{
    const int*   inputs = (const int*)  d_in[0];
    const float* emb    = (const float*)d_in[1];
    const float* Wi     = (const float*)d_in[2];
    const float* Wh     = (const float*)d_in[3];
    const float* bvec   = (const float*)d_in[4];
    const float* W1     = (const float*)d_in[5];
    const float* b1     = (const float*)d_in[6];
    const float* W2     = (const float*)d_in[7];
    const float* b2     = (const float*)d_in[8];
    const float* W3     = (const float*)d_in[9];
    const float* b3     = (const float*)d_in[10];
    float* out = (float*)d_out;

    void *p_h = 0, *p_y1 = 0, *p_y2 = 0, *p_lg = 0;
    cudaGetSymbolAddress(&p_h,  g_hT);     // final h in g_hT[0], k-major [u][b]
    cudaGetSymbolAddress(&p_y1, g_y1);
    cudaGetSymbolAddress(&p_y2, g_y2);
    cudaGetSymbolAddress(&p_lg, g_logits);

    // 1. Z = emb[inputs] @ Wi + b  (time-parallel)
    embed_gemm_kernel<<<dim3(GATES / 128, (SEQ * BATCH) / 128), 256>>>(inputs, emb, Wi, bvec);

    // 2. persistent LSTM recurrence
    cudaFuncSetAttribute(lstm_kernel, cudaFuncAttributeMaxDynamicSharedMemorySize, LSTM_SMEM);
    lstm_kernel<<<NBLK, 256, LSTM_SMEM>>>(Wh);

    // 3/4. dense tanh layers (fc1 reads k-major h)
    fc_tanh_kernel<64, 1><<<128, 256>>>((const float*)p_h,  W1, b1, (float*)p_y1);
    fc_tanh_kernel<1, 512><<<128, 256>>>((const float*)p_y1, W2, b2, (float*)p_y2);

    // 5. vocab projection
    logits_kernel<<<(VOCAB + 127) / 128, 128>>>((const float*)p_y2, W3, b3, (float*)p_lg);

    // 6. log_softmax
    logsoftmax_kernel<<<BATCH, 1024>>>((const float*)p_lg, out);
}

// round 12
// speedup vs baseline: 1.2101x; 1.0099x over previous
#include <cuda_runtime.h>
#include <math.h>

// ---------------- problem constants ----------------
#define BATCH   64
#define SEQ     512
#define EMB     256
#define HID     512
#define GATES   2048           // 4*HID
#define VOCAB   50257
#define NBLK    128            // persistent LSTM grid (<=148 SMs, 1 block/SM)

// ---------------- device scratch (static, no allocs) ----------------
__device__ float g_Z[(size_t)SEQ * BATCH * GATES];   // 256 MB: x@Wi + b, [s][b][4H]
__device__ float g_hT[2][HID * BATCH];               // hidden state, k-major [u][b]
__device__ float g_y1[BATCH * HID];
__device__ float g_y2[BATCH * HID];
__device__ float g_logits[(size_t)BATCH * VOCAB];
// 4 independent batch-quarter barriers, each on its own 128B line.
// Sense-reversing: after 512 steps (even) state returns to 0 -> replay-safe.
__device__ unsigned g_bar_cnt4[4 * 32];
__device__ unsigned g_bar_sense4[4 * 32];

// ---------------- packed f32x2 helpers (FFMA2 path, sm_100+) --------------
__device__ __forceinline__ unsigned long long fma2(unsigned long long a,
                                                   unsigned long long b,
                                                   unsigned long long c)
{
    unsigned long long d;
    asm("fma.rn.f32x2 %0, %1, %2, %3;" : "=l"(d) : "l"(a), "l"(b), "l"(c));
    return d;
}
__device__ __forceinline__ unsigned long long pack2(float x)
{
    unsigned long long d;
    unsigned u = __float_as_uint(x);
    asm("mov.b64 %0, {%1, %1};" : "=l"(d) : "r"(u));
    return d;
}
__device__ __forceinline__ float lo2(unsigned long long v) { return __uint_as_float((unsigned)v); }
__device__ __forceinline__ float hi2(unsigned long long v) { return __uint_as_float((unsigned)(v >> 32)); }

// ---------------- fast activations (MUFU.TANH) ----------------
__device__ __forceinline__ float tanh_fast(float x)
{
    float y;
    asm("tanh.approx.f32 %0, %1;" : "=f"(y) : "f"(x));
    return y;
}
__device__ __forceinline__ float sigmoid_fast(float x)
{
    return 0.5f * tanh_fast(0.5f * x) + 0.5f;
}

// ---------------- cp.async helpers ----------------
__device__ __forceinline__ void cp16(unsigned dst_u32, const void* src)
{
    asm volatile("cp.async.cg.shared.global [%0], [%1], 16;"
                 :: "r"(dst_u32), "l"(src) : "memory");
}
__device__ __forceinline__ void cp_commit()
{
    asm volatile("cp.async.commit_group;" ::: "memory");
}
__device__ __forceinline__ void cp_wait0()
{
    asm volatile("cp.async.wait_group 0;" ::: "memory");
}

// ---------------- group grid barrier (R7 pattern, n arrivals) --------------
__device__ __forceinline__ void grid_barrier_g(unsigned &sense, unsigned* cnt,
                                               unsigned* flag, unsigned n)
{
    __syncthreads();
    if (threadIdx.x == 0) {
        sense ^= 1u;
        unsigned old;
        asm volatile("atom.add.release.gpu.global.u32 %0, [%1], %2;"
                     : "=r"(old) : "l"(cnt), "r"(1u) : "memory");
        if (old == n - 1u) {
            asm volatile("st.global.relaxed.gpu.u32 [%0], %1;"
                         :: "l"(cnt), "r"(0u) : "memory");
            asm volatile("st.global.release.gpu.u32 [%0], %1;"
                         :: "l"(flag), "r"(sense) : "memory");
        } else {
            unsigned v;
            do {
                asm volatile("ld.global.acquire.gpu.u32 %0, [%1];"
                             : "=r"(v) : "l"(flag) : "memory");
            } while (v != sense);
        }
    }
    __syncthreads();
}

// ---------------- kernel 1: Z = gather(emb, inputs) @ Wi + b --------------
// (R2-proven, unchanged) 128x128 tile, K-chunks of 16, 8x8 thread tile, f32x2.
__global__ void __launch_bounds__(256, 2)
embed_gemm_kernel(const int* __restrict__ inputs, const float* __restrict__ emb,
                  const float* __restrict__ Wi, const float* __restrict__ bias)
{
    __shared__ float As[128][17];
    __shared__ float Bs[16][132];

    const int t  = threadIdx.x;
    const int mt = blockIdx.y;
    const int nt = blockIdx.x;
    const int tx = t & 15;
    const int ty = t >> 4;

    const int ra   = t >> 1;
    const int koff = (t & 1) * 8;
    const int rowg = mt * 128 + ra;
    const int s    = rowg >> 6;
    const int b    = rowg & 63;
    const float* erow = emb + (size_t)inputs[b * SEQ + s] * EMB;

    const int bkr  = t >> 4;
    const int bcol = (t & 15) * 8;

    unsigned long long acc[8][4];
#pragma unroll
    for (int i = 0; i < 8; ++i)
#pragma unroll
        for (int j = 0; j < 4; ++j) acc[i][j] = 0ULL;

    for (int k0 = 0; k0 < EMB; k0 += 16) {
        {
            float4 a0 = *(const float4*)(erow + k0 + koff);
            float4 a1 = *(const float4*)(erow + k0 + koff + 4);
            As[ra][koff + 0] = a0.x; As[ra][koff + 1] = a0.y;
            As[ra][koff + 2] = a0.z; As[ra][koff + 3] = a0.w;
            As[ra][koff + 4] = a1.x; As[ra][koff + 5] = a1.y;
            As[ra][koff + 6] = a1.z; As[ra][koff + 7] = a1.w;
        }
        {
            const float* wsrc = Wi + (size_t)(k0 + bkr) * GATES + nt * 128 + bcol;
            float4 b0v = *(const float4*)(wsrc);
            float4 b1v = *(const float4*)(wsrc + 4);
            *(float4*)&Bs[bkr][bcol]     = b0v;
            *(float4*)&Bs[bkr][bcol + 4] = b1v;
        }
        __syncthreads();

#pragma unroll
        for (int k = 0; k < 16; ++k) {
            unsigned long long pa[8];
#pragma unroll
            for (int i = 0; i < 4; ++i) {
                pa[i]     = pack2(As[ty * 4 + i][k]);
                pa[i + 4] = pack2(As[64 + ty * 4 + i][k]);
            }
            ulonglong2 b0v = *(const ulonglong2*)&Bs[k][tx * 4];
            ulonglong2 b1v = *(const ulonglong2*)&Bs[k][64 + tx * 4];
#pragma unroll
            for (int i = 0; i < 8; ++i) {
                acc[i][0] = fma2(pa[i], b0v.x, acc[i][0]);
                acc[i][1] = fma2(pa[i], b0v.y, acc[i][1]);
                acc[i][2] = fma2(pa[i], b1v.x, acc[i][2]);
                acc[i][3] = fma2(pa[i], b1v.y, acc[i][3]);
            }
        }
        __syncthreads();
    }

    float4 bb0 = *(const float4*)(bias + nt * 128 + tx * 4);
    float4 bb1 = *(const float4*)(bias + nt * 128 + 64 + tx * 4);
#pragma unroll
    for (int i = 0; i < 8; ++i) {
        int row = mt * 128 + ((i < 4) ? (ty * 4 + i) : (64 + ty * 4 + i - 4));
        float* zr = g_Z + (size_t)row * GATES + nt * 128;
        float4 v0, v1;
        v0.x = lo2(acc[i][0]) + bb0.x; v0.y = hi2(acc[i][0]) + bb0.y;
        v0.z = lo2(acc[i][1]) + bb0.z; v0.w = hi2(acc[i][1]) + bb0.w;
        v1.x = lo2(acc[i][2]) + bb1.x; v1.y = hi2(acc[i][2]) + bb1.y;
        v1.z = lo2(acc[i][3]) + bb1.z; v1.w = hi2(acc[i][3]) + bb1.w;
        *(float4*)(zr + tx * 4)      = v0;
        *(float4*)(zr + 64 + tx * 4) = v1;
    }
}

// ---------------- kernel 2: persistent LSTM over 512 steps ----------------
// (R11-proven, unchanged) 128 blocks = 32 unit-groups x 4 batch-quarters;
// block = 16 units x 16 batches; warp = kc strip (broadcast LDS);
// warp-private cp.async staging; 4 independent quarter barriers.
#define LSTM_SMEM (32768 + 131072 + 36864)

__global__ void __launch_bounds__(256, 1)
lstm_kernel(const float* __restrict__ Wh)
{
    extern __shared__ float sm[];
    float4*     h_s4 = (float4*)sm;                           // [512][4]
    ulonglong2* Whs  = (ulonglong2*)((char*)sm + 32768);      // [512][16]
    ulonglong2* red  = (ulonglong2*)((char*)sm + 163840);     // [256 p][9]

    const int tid  = threadIdx.x;
    const int kc   = tid >> 5;           // warp id = k-strip 0..7 (64 k each)
    const int lane = tid & 31;
    const int up   = lane >> 2;          // unit pair 0..7 (units 2up, 2up+1)
    const int bg   = lane & 3;           // batch group 0..3 (4 batches)
    const int ub   = blockIdx.x >> 2;    // unit group 0..31 (16 units)
    const int q    = blockIdx.x & 3;     // batch quarter 0..3 (16 batches)
    const unsigned h_s_u32 = (unsigned)__cvta_generic_to_shared(h_s4);

    unsigned* cntp  = &g_bar_cnt4[q * 32];
    unsigned* snsp  = &g_bar_sense4[q * 32];

    // epilogue ownership: pair p = tid -> unit u_local, batch b_local
    const int eul = tid >> 4;            // 0..15
    const int ebl = tid & 15;            // 0..15
    const int euu = ub * 16 + eul;       // global unit
    const int egb = q * 16 + ebl;        // global batch

    // stage Wh slice once: Whs[k*16+u] = {(wi,wf),(wg,wo)} for col = ub*16+u
    for (int i = tid; i < HID * 16; i += 256) {
        int k = i >> 4, u2 = i & 15;
        const float* w = Wh + (size_t)k * GATES + ub * 16 + u2;
        float4 v = make_float4(w[0], w[512], w[1024], w[1536]);
        Whs[i] = *(ulonglong2*)&v;
    }

    float c = 0.0f;                      // cell state of pair p = tid
    unsigned sense = 0;
    __syncthreads();

    const ulonglong2* wp = Whs  + kc * 1024 + up * 2;  // iter i: wp[i*16], +1
    const float4*     hp = h_s4 + kc * 256 + bg;       // iter i: hp[i*4]

    // warp-private staging: warp kc owns f4-chunks [kc*256, kc*256+256)
    const int cbase = kc * 256 + lane;                 // 8 chunks per lane

    // Z prefetch for step 0 (gates for pair p)
    const float* z0 = g_Z + (size_t)egb * GATES + euu;
    float zi = __ldcg(z0), zf = __ldcg(z0 + 512);
    float zg = __ldcg(z0 + 1024), zo = __ldcg(z0 + 1536);

    for (int s = 0; s < SEQ; ++s) {
        unsigned long long aif[2][4] = {{0,0,0,0},{0,0,0,0}};
        unsigned long long ago[2][4] = {{0,0,0,0},{0,0,0,0}};

        if (s > 0) {
            // ---- warp-private staging of this warp's h strip (4KB) ----
            const float4* src4 = (const float4*)g_hT[s & 1];
#pragma unroll
            for (int j = 0; j < 8; ++j) {
                int chunk = cbase + j * 32;             // within own strip
                int k = chunk >> 2, cc = chunk & 3;
                cp16(h_s_u32 + chunk * 16, src4 + k * 16 + q * 4 + cc);
            }
            cp_commit();
            cp_wait0();        // own 8 copies landed
            __syncwarp();      // all 32 lanes done -> strip complete

            // ---- mainloop: k fixed per iteration, all LDS broadcast ----
#pragma unroll 4
            for (int i = 0; i < 64; ++i) {
                ulonglong2 w0 = wp[i * 16];      // unit 2up   (wi,wf),(wg,wo)
                ulonglong2 w1 = wp[i * 16 + 1];  // unit 2up+1
                float4     hv = hp[i * 4];       // 4 batches
                unsigned long long p;
                p = pack2(hv.x);
                aif[0][0] = fma2(p, w0.x, aif[0][0]); ago[0][0] = fma2(p, w0.y, ago[0][0]);
                aif[1][0] = fma2(p, w1.x, aif[1][0]); ago[1][0] = fma2(p, w1.y, ago[1][0]);
                p = pack2(hv.y);
                aif[0][1] = fma2(p, w0.x, aif[0][1]); ago[0][1] = fma2(p, w0.y, ago[0][1]);
                aif[1][1] = fma2(p, w1.x, aif[1][1]); ago[1][1] = fma2(p, w1.y, ago[1][1]);
                p = pack2(hv.z);
                aif[0][2] = fma2(p, w0.x, aif[0][2]); ago[0][2] = fma2(p, w0.y, ago[0][2]);
                aif[1][2] = fma2(p, w1.x, aif[1][2]); ago[1][2] = fma2(p, w1.y, ago[1][2]);
                p = pack2(hv.w);
                aif[0][3] = fma2(p, w0.x, aif[0][3]); ago[0][3] = fma2(p, w0.y, ago[0][3]);
                aif[1][3] = fma2(p, w1.x, aif[1][3]); ago[1][3] = fma2(p, w1.y, ago[1][3]);
            }
        }

        // ---- write partials to skewed red[p*9 + kc] ----
#pragma unroll
        for (int uo = 0; uo < 2; ++uo)
#pragma unroll
            for (int bi = 0; bi < 4; ++bi) {
                int p = (2 * up + uo) * 16 + bg * 4 + bi;
                red[p * 9 + kc] = make_ulonglong2(aif[uo][bi], ago[uo][bi]);
            }
        __syncthreads();

        // ---- reduce 8 kc partials for pair p = tid; epilogue ----
        {
            float fi = zi, ff = zf, fg_ = zg, fo = zo;
#pragma unroll
            for (int k8 = 0; k8 < 8; ++k8) {
                ulonglong2 v = red[tid * 9 + k8];
                fi += lo2(v.x); ff += hi2(v.x);
                fg_ += lo2(v.y); fo += hi2(v.y);
            }
            float ig  = sigmoid_fast(fi);
            float fg2 = sigmoid_fast(ff);
            float gg  = tanh_fast(fg_);
            float og  = sigmoid_fast(fo);
            c = fg2 * c + ig * gg;
            float hv = og * tanh_fast(c);
            g_hT[(s + 1) & 1][euu * 64 + egb] = hv;    // final h in g_hT[0]
        }

        // ---- prefetch Z for step s+1 (hides DRAM latency behind barrier) --
        if (s + 1 < SEQ) {
            const float* z = g_Z + ((size_t)(s + 1) * BATCH + egb) * GATES + euu;
            zi = __ldcg(z);        zf = __ldcg(z + 512);
            zg = __ldcg(z + 1024); zo = __ldcg(z + 1536);
        }

        grid_barrier_g(sense, cntp, snsp, 32u);   // only this batch quarter
    }
}

// ---------------- kernels 3/4: y = tanh(x @ W + bias), 64x512 --------------
// NEW: block = one batch row (64 blocks x 512 threads). x row staged in smem
// once (broadcast LDS in k-loop); W reads coalesced across j; 4 accumulators.
template<int SK, int SB>
__global__ void __launch_bounds__(512)
fc_tanh_kernel(const float* __restrict__ x, const float* __restrict__ W,
               const float* __restrict__ bias, float* __restrict__ y)
{
    __shared__ float xs[HID];
    const int b = blockIdx.x;
    const int j = threadIdx.x;

    xs[j] = x[j * SK + b * SB];
    __syncthreads();

    float a0 = 0.f, a1 = 0.f, a2 = 0.f, a3 = 0.f;
#pragma unroll 4
    for (int k = 0; k < HID; k += 4) {
        a0 += xs[k + 0] * W[(size_t)(k + 0) * HID + j];
        a1 += xs[k + 1] * W[(size_t)(k + 1) * HID + j];
        a2 += xs[k + 2] * W[(size_t)(k + 2) * HID + j];
        a3 += xs[k + 3] * W[(size_t)(k + 3) * HID + j];
    }
    y[b * HID + j] = tanhf((a0 + a1) + (a2 + a3) + bias[j]);
}

// ---------------- kernel 5: logits = y2 @ W3 + b3 (f32x2 accumulators) -----
// 128 threads/block, 1 vocab column per thread, 64 batches as 32 packed
// f32x2 accumulators -> fma-issue count halves vs scalar FFMA.
__global__ void __launch_bounds__(128)
logits_kernel(const float* __restrict__ y, const float* __restrict__ W3,
              const float* __restrict__ b3, float* __restrict__ out)
{
    __shared__ __align__(16) float ys[128][68];   // [k][b], row = 272B (16B-mult)
    const int j = blockIdx.x * 128 + threadIdx.x;

    unsigned long long acc[32];
#pragma unroll
    for (int i = 0; i < 32; ++i) acc[i] = 0ULL;

    for (int kc = 0; kc < HID; kc += 128) {
        __syncthreads();
        for (int qq = threadIdx.x; qq < 128 * 64; qq += 128) {
            int b = qq >> 7, k = qq & 127;
            ys[k][b] = y[b * HID + kc + k];
        }
        __syncthreads();
        if (j < VOCAB) {
#pragma unroll 4
            for (int k = 0; k < 128; ++k) {
                unsigned long long wpk = pack2(W3[(size_t)(kc + k) * VOCAB + j]);
                const ulonglong2* yr = (const ulonglong2*)&ys[k][0];
#pragma unroll
                for (int b2 = 0; b2 < 16; ++b2) {
                    ulonglong2 v = yr[b2];                  // batches 4b2..4b2+3
                    acc[b2 * 2]     = fma2(wpk, v.x, acc[b2 * 2]);
                    acc[b2 * 2 + 1] = fma2(wpk, v.y, acc[b2 * 2 + 1]);
                }
            }
        }
    }
    if (j < VOCAB) {
        float bb = b3[j];
#pragma unroll
        for (int i = 0; i < 32; ++i) {
            out[(size_t)(2 * i)     * VOCAB + j] = lo2(acc[i]) + bb;
            out[(size_t)(2 * i + 1) * VOCAB + j] = hi2(acc[i]) + bb;
        }
    }
}

// ---------------- kernel 6: row-wise log_softmax ----------------
__global__ void __launch_bounds__(1024)
logsoftmax_kernel(const float* __restrict__ logits, float* __restrict__ out)
{
    __shared__ float red[32];
    const int b = blockIdx.x;
    const float* row  = logits + (size_t)b * VOCAB;
    float*       orow = out    + (size_t)b * VOCAB;
    const int tid = threadIdx.x;

    float m = -1e30f;
    for (int j = tid; j < VOCAB; j += 1024) m = fmaxf(m, row[j]);
#pragma unroll
    for (int o = 16; o; o >>= 1) m = fmaxf(m, __shfl_xor_sync(0xffffffffu, m, o));
    if ((tid & 31) == 0) red[tid >> 5] = m;
    __syncthreads();
    if (tid < 32) {
        float v = red[tid];
#pragma unroll
        for (int o = 16; o; o >>= 1) v = fmaxf(v, __shfl_xor_sync(0xffffffffu, v, o));
        red[tid] = v;
    }
    __syncthreads();
    m = red[0];

    float sum = 0.0f;
    for (int j = tid; j < VOCAB; j += 1024) sum += __expf(row[j] - m);
#pragma unroll
    for (int o = 16; o; o >>= 1) sum += __shfl_xor_sync(0xffffffffu, sum, o);
    __syncthreads();
    if ((tid & 31) == 0) red[tid >> 5] = sum;
    __syncthreads();
    if (tid < 32) {
        float v = red[tid];
#pragma unroll
        for (int o = 16; o; o >>= 1) v += __shfl_xor_sync(0xffffffffu, v, o);
        red[tid] = v;
    }
    __syncthreads();
    float lse = m + logf(red[0]);

    for (int j = tid; j < VOCAB; j += 1024) orow[j] = row[j] - lse;
}

// ---------------- launch ----------------
extern "C" void kernel_launch(void* const* d_in, const int* in_sizes, int n_in,
                              void* d_out, int out_size)
{
    const int*   inputs = (const int*)  d_in[0];
    const float* emb    = (const float*)d_in[1];
    const float* Wi     = (const float*)d_in[2];
    const float* Wh     = (const float*)d_in[3];
    const float* bvec   = (const float*)d_in[4];
    const float* W1     = (const float*)d_in[5];
    const float* b1     = (const float*)d_in[6];
    const float* W2     = (const float*)d_in[7];
    const float* b2     = (const float*)d_in[8];
    const float* W3     = (const float*)d_in[9];
    const float* b3     = (const float*)d_in[10];
    float* out = (float*)d_out;

    void *p_h = 0, *p_y1 = 0, *p_y2 = 0, *p_lg = 0;
    cudaGetSymbolAddress(&p_h,  g_hT);     // final h in g_hT[0], k-major [u][b]
    cudaGetSymbolAddress(&p_y1, g_y1);
    cudaGetSymbolAddress(&p_y2, g_y2);
    cudaGetSymbolAddress(&p_lg, g_logits);

    // 1. Z = emb[inputs] @ Wi + b  (time-parallel)
    embed_gemm_kernel<<<dim3(GATES / 128, (SEQ * BATCH) / 128), 256>>>(inputs, emb, Wi, bvec);

    // 2. persistent LSTM recurrence
    cudaFuncSetAttribute(lstm_kernel, cudaFuncAttributeMaxDynamicSharedMemorySize, LSTM_SMEM);
    lstm_kernel<<<NBLK, 256, LSTM_SMEM>>>(Wh);

    // 3/4. dense tanh layers (fc1 reads k-major h: x[k*64 + b])
    fc_tanh_kernel<64, 1><<<BATCH, 512>>>((const float*)p_h,  W1, b1, (float*)p_y1);
    fc_tanh_kernel<1, 512><<<BATCH, 512>>>((const float*)p_y1, W2, b2, (float*)p_y2);

    // 5. vocab projection
    logits_kernel<<<(VOCAB + 127) / 128, 128>>>((const float*)p_y2, W3, b3, (float*)p_lg);

    // 6. log_softmax
    logsoftmax_kernel<<<BATCH, 1024>>>((const float*)p_lg, out);
}

// round 13
// speedup vs baseline: 1.2207x; 1.0088x over previous
#include <cuda_runtime.h>
#include <math.h>

// ---------------- problem constants ----------------
#define BATCH   64
#define SEQ     512
#define EMB     256
#define HID     512
#define GATES   2048           // 4*HID
#define VOCAB   50257
#define NBLK    128            // persistent LSTM grid (<=148 SMs, 1 block/SM)

// ---------------- device scratch (static, no allocs) ----------------
__device__ float g_Z[(size_t)SEQ * BATCH * GATES];   // 256 MB: x@Wi + b, [s][b][4H]
__device__ float g_hQ[2][4][HID * 16];               // h, quarter-contiguous [q][u][b16]
__device__ float g_y1[BATCH * HID];
__device__ float g_y2[BATCH * HID];
__device__ float g_logits[(size_t)BATCH * VOCAB];
// 4 independent batch-quarter barriers, each on its own 128B line.
// Sense-reversing: after 512 steps (even) state returns to 0 -> replay-safe.
__device__ unsigned g_bar_cnt4[4 * 32];
__device__ unsigned g_bar_sense4[4 * 32];

// ---------------- packed f32x2 helpers (FFMA2 path, sm_100+) --------------
__device__ __forceinline__ unsigned long long fma2(unsigned long long a,
                                                   unsigned long long b,
                                                   unsigned long long c)
{
    unsigned long long d;
    asm("fma.rn.f32x2 %0, %1, %2, %3;" : "=l"(d) : "l"(a), "l"(b), "l"(c));
    return d;
}
__device__ __forceinline__ unsigned long long pack2(float x)
{
    unsigned long long d;
    unsigned u = __float_as_uint(x);
    asm("mov.b64 %0, {%1, %1};" : "=l"(d) : "r"(u));
    return d;
}
__device__ __forceinline__ float lo2(unsigned long long v) { return __uint_as_float((unsigned)v); }
__device__ __forceinline__ float hi2(unsigned long long v) { return __uint_as_float((unsigned)(v >> 32)); }

// ---------------- fast activations (MUFU.TANH) ----------------
__device__ __forceinline__ float tanh_fast(float x)
{
    float y;
    asm("tanh.approx.f32 %0, %1;" : "=f"(y) : "f"(x));
    return y;
}
__device__ __forceinline__ float sigmoid_fast(float x)
{
    return 0.5f * tanh_fast(0.5f * x) + 0.5f;
}

// ---------------- cp.async helpers ----------------
__device__ __forceinline__ void cp16(unsigned dst_u32, const void* src)
{
    asm volatile("cp.async.cg.shared.global [%0], [%1], 16;"
                 :: "r"(dst_u32), "l"(src) : "memory");
}
__device__ __forceinline__ void cp_commit()
{
    asm volatile("cp.async.commit_group;" ::: "memory");
}
__device__ __forceinline__ void cp_wait0()
{
    asm volatile("cp.async.wait_group 0;" ::: "memory");
}

// ---------------- group grid barrier (R7 pattern, n arrivals) --------------
__device__ __forceinline__ void grid_barrier_g(unsigned &sense, unsigned* cnt,
                                               unsigned* flag, unsigned n)
{
    __syncthreads();
    if (threadIdx.x == 0) {
        sense ^= 1u;
        unsigned old;
        asm volatile("atom.add.release.gpu.global.u32 %0, [%1], %2;"
                     : "=r"(old) : "l"(cnt), "r"(1u) : "memory");
        if (old == n - 1u) {
            asm volatile("st.global.relaxed.gpu.u32 [%0], %1;"
                         :: "l"(cnt), "r"(0u) : "memory");
            asm volatile("st.global.release.gpu.u32 [%0], %1;"
                         :: "l"(flag), "r"(sense) : "memory");
        } else {
            unsigned v;
            do {
                asm volatile("ld.global.acquire.gpu.u32 %0, [%1];"
                             : "=r"(v) : "l"(flag) : "memory");
            } while (v != sense);
        }
    }
    __syncthreads();
}

// ---------------- kernel 1: Z = gather(emb, inputs) @ Wi + b --------------
// (R2-proven, unchanged) 128x128 tile, K-chunks of 16, 8x8 thread tile, f32x2.
__global__ void __launch_bounds__(256, 2)
embed_gemm_kernel(const int* __restrict__ inputs, const float* __restrict__ emb,
                  const float* __restrict__ Wi, const float* __restrict__ bias)
{
    __shared__ float As[128][17];
    __shared__ float Bs[16][132];

    const int t  = threadIdx.x;
    const int mt = blockIdx.y;
    const int nt = blockIdx.x;
    const int tx = t & 15;
    const int ty = t >> 4;

    const int ra   = t >> 1;
    const int koff = (t & 1) * 8;
    const int rowg = mt * 128 + ra;
    const int s    = rowg >> 6;
    const int b    = rowg & 63;
    const float* erow = emb + (size_t)inputs[b * SEQ + s] * EMB;

    const int bkr  = t >> 4;
    const int bcol = (t & 15) * 8;

    unsigned long long acc[8][4];
#pragma unroll
    for (int i = 0; i < 8; ++i)
#pragma unroll
        for (int j = 0; j < 4; ++j) acc[i][j] = 0ULL;

    for (int k0 = 0; k0 < EMB; k0 += 16) {
        {
            float4 a0 = *(const float4*)(erow + k0 + koff);
            float4 a1 = *(const float4*)(erow + k0 + koff + 4);
            As[ra][koff + 0] = a0.x; As[ra][koff + 1] = a0.y;
            As[ra][koff + 2] = a0.z; As[ra][koff + 3] = a0.w;
            As[ra][koff + 4] = a1.x; As[ra][koff + 5] = a1.y;
            As[ra][koff + 6] = a1.z; As[ra][koff + 7] = a1.w;
        }
        {
            const float* wsrc = Wi + (size_t)(k0 + bkr) * GATES + nt * 128 + bcol;
            float4 b0v = *(const float4*)(wsrc);
            float4 b1v = *(const float4*)(wsrc + 4);
            *(float4*)&Bs[bkr][bcol]     = b0v;
            *(float4*)&Bs[bkr][bcol + 4] = b1v;
        }
        __syncthreads();

#pragma unroll
        for (int k = 0; k < 16; ++k) {
            unsigned long long pa[8];
#pragma unroll
            for (int i = 0; i < 4; ++i) {
                pa[i]     = pack2(As[ty * 4 + i][k]);
                pa[i + 4] = pack2(As[64 + ty * 4 + i][k]);
            }
            ulonglong2 b0v = *(const ulonglong2*)&Bs[k][tx * 4];
            ulonglong2 b1v = *(const ulonglong2*)&Bs[k][64 + tx * 4];
#pragma unroll
            for (int i = 0; i < 8; ++i) {
                acc[i][0] = fma2(pa[i], b0v.x, acc[i][0]);
                acc[i][1] = fma2(pa[i], b0v.y, acc[i][1]);
                acc[i][2] = fma2(pa[i], b1v.x, acc[i][2]);
                acc[i][3] = fma2(pa[i], b1v.y, acc[i][3]);
            }
        }
        __syncthreads();
    }

    float4 bb0 = *(const float4*)(bias + nt * 128 + tx * 4);
    float4 bb1 = *(const float4*)(bias + nt * 128 + 64 + tx * 4);
#pragma unroll
    for (int i = 0; i < 8; ++i) {
        int row = mt * 128 + ((i < 4) ? (ty * 4 + i) : (64 + ty * 4 + i - 4));
        float* zr = g_Z + (size_t)row * GATES + nt * 128;
        float4 v0, v1;
        v0.x = lo2(acc[i][0]) + bb0.x; v0.y = hi2(acc[i][0]) + bb0.y;
        v0.z = lo2(acc[i][1]) + bb0.z; v0.w = hi2(acc[i][1]) + bb0.w;
        v1.x = lo2(acc[i][2]) + bb1.x; v1.y = hi2(acc[i][2]) + bb1.y;
        v1.z = lo2(acc[i][3]) + bb1.z; v1.w = hi2(acc[i][3]) + bb1.w;
        *(float4*)(zr + tx * 4)      = v0;
        *(float4*)(zr + 64 + tx * 4) = v1;
    }
}

// ---------------- kernel 2: persistent LSTM over 512 steps ----------------
// (R11/R12-proven core) 128 blocks = 32 unit-groups x 4 batch-quarters;
// block = 16 units x 16 batches; warp = kc strip (broadcast LDS);
// warp-private cp.async staging; 4 independent quarter barriers.
// NEW vs R12: h stored QUARTER-CONTIGUOUS (g_hQ[buf][q][u][b16]) -> staging
// reads a dense 32KB block with full 128B-line utilization (halves L2 sector
// traffic vs the old [u][b64] layout where each 64B chunk wasted half a line).
#define LSTM_SMEM (32768 + 131072 + 36864)

__global__ void __launch_bounds__(256, 1)
lstm_kernel(const float* __restrict__ Wh)
{
    extern __shared__ float sm[];
    float4*     h_s4 = (float4*)sm;                           // [512][4]
    ulonglong2* Whs  = (ulonglong2*)((char*)sm + 32768);      // [512][16]
    ulonglong2* red  = (ulonglong2*)((char*)sm + 163840);     // [256 p][9]

    const int tid  = threadIdx.x;
    const int kc   = tid >> 5;           // warp id = k-strip 0..7 (64 k each)
    const int lane = tid & 31;
    const int up   = lane >> 2;          // unit pair 0..7 (units 2up, 2up+1)
    const int bg   = lane & 3;           // batch group 0..3 (4 batches)
    const int ub   = blockIdx.x >> 2;    // unit group 0..31 (16 units)
    const int q    = blockIdx.x & 3;     // batch quarter 0..3 (16 batches)
    const unsigned h_s_u32 = (unsigned)__cvta_generic_to_shared(h_s4);

    unsigned* cntp  = &g_bar_cnt4[q * 32];
    unsigned* snsp  = &g_bar_sense4[q * 32];

    // epilogue ownership: pair p = tid -> unit u_local, batch b_local
    const int eul = tid >> 4;            // 0..15
    const int ebl = tid & 15;            // 0..15
    const int euu = ub * 16 + eul;       // global unit
    const int egb = q * 16 + ebl;        // global batch

    // stage Wh slice once: Whs[k*16+u] = {(wi,wf),(wg,wo)} for col = ub*16+u
    for (int i = tid; i < HID * 16; i += 256) {
        int k = i >> 4, u2 = i & 15;
        const float* w = Wh + (size_t)k * GATES + ub * 16 + u2;
        float4 v = make_float4(w[0], w[512], w[1024], w[1536]);
        Whs[i] = *(ulonglong2*)&v;
    }

    float c = 0.0f;                      // cell state of pair p = tid
    unsigned sense = 0;
    __syncthreads();

    const ulonglong2* wp = Whs  + kc * 1024 + up * 2;  // iter i: wp[i*16], +1
    const float4*     hp = h_s4 + kc * 256 + bg;       // iter i: hp[i*4]

    // warp-private staging: warp kc owns f4-chunks [kc*256, kc*256+256).
    // Quarter slice is DENSE: chunk index == smem f4 index == src f4 index.
    const int cbase = kc * 256 + lane;                 // 8 chunks per lane

    // Z prefetch for step 0 (gates for pair p)
    const float* z0 = g_Z + (size_t)egb * GATES + euu;
    float zi = __ldcg(z0), zf = __ldcg(z0 + 512);
    float zg = __ldcg(z0 + 1024), zo = __ldcg(z0 + 1536);

    for (int s = 0; s < SEQ; ++s) {
        unsigned long long aif[2][4] = {{0,0,0,0},{0,0,0,0}};
        unsigned long long ago[2][4] = {{0,0,0,0},{0,0,0,0}};

        if (s > 0) {
            // ---- warp-private staging of this warp's h strip (4KB, dense) --
            const float4* src4 = (const float4*)g_hQ[s & 1][q];
#pragma unroll
            for (int j = 0; j < 8; ++j) {
                int chunk = cbase + j * 32;             // within own strip
                cp16(h_s_u32 + chunk * 16, src4 + chunk);
            }
            cp_commit();
            cp_wait0();        // own 8 copies landed
            __syncwarp();      // all 32 lanes done -> strip complete

            // ---- mainloop: k fixed per iteration, all LDS broadcast ----
#pragma unroll 4
            for (int i = 0; i < 64; ++i) {
                ulonglong2 w0 = wp[i * 16];      // unit 2up   (wi,wf),(wg,wo)
                ulonglong2 w1 = wp[i * 16 + 1];  // unit 2up+1
                float4     hv = hp[i * 4];       // 4 batches
                unsigned long long p;
                p = pack2(hv.x);
                aif[0][0] = fma2(p, w0.x, aif[0][0]); ago[0][0] = fma2(p, w0.y, ago[0][0]);
                aif[1][0] = fma2(p, w1.x, aif[1][0]); ago[1][0] = fma2(p, w1.y, ago[1][0]);
                p = pack2(hv.y);
                aif[0][1] = fma2(p, w0.x, aif[0][1]); ago[0][1] = fma2(p, w0.y, ago[0][1]);
                aif[1][1] = fma2(p, w1.x, aif[1][1]); ago[1][1] = fma2(p, w1.y, ago[1][1]);
                p = pack2(hv.z);
                aif[0][2] = fma2(p, w0.x, aif[0][2]); ago[0][2] = fma2(p, w0.y, ago[0][2]);
                aif[1][2] = fma2(p, w1.x, aif[1][2]); ago[1][2] = fma2(p, w1.y, ago[1][2]);
                p = pack2(hv.w);
                aif[0][3] = fma2(p, w0.x, aif[0][3]); ago[0][3] = fma2(p, w0.y, ago[0][3]);
                aif[1][3] = fma2(p, w1.x, aif[1][3]); ago[1][3] = fma2(p, w1.y, ago[1][3]);
            }
        }

        // ---- write partials to skewed red[p*9 + kc] ----
#pragma unroll
        for (int uo = 0; uo < 2; ++uo)
#pragma unroll
            for (int bi = 0; bi < 4; ++bi) {
                int p = (2 * up + uo) * 16 + bg * 4 + bi;
                red[p * 9 + kc] = make_ulonglong2(aif[uo][bi], ago[uo][bi]);
            }
        __syncthreads();

        // ---- reduce 8 kc partials for pair p = tid; epilogue ----
        {
            float fi = zi, ff = zf, fg_ = zg, fo = zo;
#pragma unroll
            for (int k8 = 0; k8 < 8; ++k8) {
                ulonglong2 v = red[tid * 9 + k8];
                fi += lo2(v.x); ff += hi2(v.x);
                fg_ += lo2(v.y); fo += hi2(v.y);
            }
            float ig  = sigmoid_fast(fi);
            float fg2 = sigmoid_fast(ff);
            float gg  = tanh_fast(fg_);
            float og  = sigmoid_fast(fo);
            c = fg2 * c + ig * gg;
            float hv = og * tanh_fast(c);
            // quarter-contiguous store: [q][u][b16]; final h in g_hQ[0]
            g_hQ[(s + 1) & 1][q][euu * 16 + ebl] = hv;
        }

        // ---- prefetch Z for step s+1 (hides DRAM latency behind barrier) --
        if (s + 1 < SEQ) {
            const float* z = g_Z + ((size_t)(s + 1) * BATCH + egb) * GATES + euu;
            zi = __ldcg(z);        zf = __ldcg(z + 512);
            zg = __ldcg(z + 1024); zo = __ldcg(z + 1536);
        }

        grid_barrier_g(sense, cntp, snsp, 32u);   // only this batch quarter
    }
}

// ---------------- kernels 3/4: y = tanh(x @ W + bias), 64x512 --------------
// Block = one batch row (64 blocks x 512 threads); x row staged in smem.
// KM=1: x is quarter-contiguous h (g_hQ[0]): x[(b>>4)*8192 + (b&15) + k*16].
// KM=0: x is batch-major [b][k]: x[b*512 + k].
template<int KM>
__global__ void __launch_bounds__(512)
fc_tanh_kernel(const float* __restrict__ x, const float* __restrict__ W,
               const float* __restrict__ bias, float* __restrict__ y)
{
    __shared__ float xs[HID];
    const int b = blockIdx.x;
    const int j = threadIdx.x;

    if (KM == 1)
        xs[j] = x[(b >> 4) * 8192 + (b & 15) + j * 16];
    else
        xs[j] = x[b * HID + j];
    __syncthreads();

    float a0 = 0.f, a1 = 0.f, a2 = 0.f, a3 = 0.f;
#pragma unroll 4
    for (int k = 0; k < HID; k += 4) {
        a0 += xs[k + 0] * W[(size_t)(k + 0) * HID + j];
        a1 += xs[k + 1] * W[(size_t)(k + 1) * HID + j];
        a2 += xs[k + 2] * W[(size_t)(k + 2) * HID + j];
        a3 += xs[k + 3] * W[(size_t)(k + 3) * HID + j];
    }
    y[b * HID + j] = tanhf((a0 + a1) + (a2 + a3) + bias[j]);
}

// ---------------- kernel 5: logits = y2 @ W3 + b3 (f32x2 accumulators) -----
__global__ void __launch_bounds__(128)
logits_kernel(const float* __restrict__ y, const float* __restrict__ W3,
              const float* __restrict__ b3, float* __restrict__ out)
{
    __shared__ __align__(16) float ys[128][68];   // [k][b], row = 272B (16B-mult)
    const int j = blockIdx.x * 128 + threadIdx.x;

    unsigned long long acc[32];
#pragma unroll
    for (int i = 0; i < 32; ++i) acc[i] = 0ULL;

    for (int kc = 0; kc < HID; kc += 128) {
        __syncthreads();
        for (int qq = threadIdx.x; qq < 128 * 64; qq += 128) {
            int b = qq >> 7, k = qq & 127;
            ys[k][b] = y[b * HID + kc + k];
        }
        __syncthreads();
        if (j < VOCAB) {
#pragma unroll 4
            for (int k = 0; k < 128; ++k) {
                unsigned long long wpk = pack2(W3[(size_t)(kc + k) * VOCAB + j]);
                const ulonglong2* yr = (const ulonglong2*)&ys[k][0];
#pragma unroll
                for (int b2 = 0; b2 < 16; ++b2) {
                    ulonglong2 v = yr[b2];                  // batches 4b2..4b2+3
                    acc[b2 * 2]     = fma2(wpk, v.x, acc[b2 * 2]);
                    acc[b2 * 2 + 1] = fma2(wpk, v.y, acc[b2 * 2 + 1]);
                }
            }
        }
    }
    if (j < VOCAB) {
        float bb = b3[j];
#pragma unroll
        for (int i = 0; i < 32; ++i) {
            out[(size_t)(2 * i)     * VOCAB + j] = lo2(acc[i]) + bb;
            out[(size_t)(2 * i + 1) * VOCAB + j] = hi2(acc[i]) + bb;
        }
    }
}

// ---------------- kernel 6: row-wise log_softmax ----------------
__global__ void __launch_bounds__(1024)
logsoftmax_kernel(const float* __restrict__ logits, float* __restrict__ out)
{
    __shared__ float red[32];
    const int b = blockIdx.x;
    const float* row  = logits + (size_t)b * VOCAB;
    float*       orow = out    + (size_t)b * VOCAB;
    const int tid = threadIdx.x;

    float m = -1e30f;
    for (int j = tid; j < VOCAB; j += 1024) m = fmaxf(m, row[j]);
#pragma unroll
    for (int o = 16; o; o >>= 1) m = fmaxf(m, __shfl_xor_sync(0xffffffffu, m, o));
    if ((tid & 31) == 0) red[tid >> 5] = m;
    __syncthreads();
    if (tid < 32) {
        float v = red[tid];
#pragma unroll
        for (int o = 16; o; o >>= 1) v = fmaxf(v, __shfl_xor_sync(0xffffffffu, v, o));
        red[tid] = v;
    }
    __syncthreads();
    m = red[0];

    float sum = 0.0f;
    for (int j = tid; j < VOCAB; j += 1024) sum += __expf(row[j] - m);
#pragma unroll
    for (int o = 16; o; o >>= 1) sum += __shfl_xor_sync(0xffffffffu, sum, o);
    __syncthreads();
    if ((tid & 31) == 0) red[tid >> 5] = sum;
    __syncthreads();
    if (tid < 32) {
        float v = red[tid];
#pragma unroll
        for (int o = 16; o; o >>= 1) v += __shfl_xor_sync(0xffffffffu, v, o);
        red[tid] = v;
    }
    __syncthreads();
    float lse = m + logf(red[0]);

    for (int j = tid; j < VOCAB; j += 1024) orow[j] = row[j] - lse;
}

// ---------------- launch ----------------
extern "C" void kernel_launch(void* const* d_in, const int* in_sizes, int n_in,
                              void* d_out, int out_size)
{
    const int*   inputs = (const int*)  d_in[0];
    const float* emb    = (const float*)d_in[1];
    const float* Wi     = (const float*)d_in[2];
    const float* Wh     = (const float*)d_in[3];
    const float* bvec   = (const float*)d_in[4];
    const float* W1     = (const float*)d_in[5];
    const float* b1     = (const float*)d_in[6];
    const float* W2     = (const float*)d_in[7];
    const float* b2     = (const float*)d_in[8];
    const float* W3     = (const float*)d_in[9];
    const float* b3     = (const float*)d_in[10];
    float* out = (float*)d_out;

    void *p_h = 0, *p_y1 = 0, *p_y2 = 0, *p_lg = 0;
    cudaGetSymbolAddress(&p_h,  g_hQ);     // final h in g_hQ[0], [q][u][b16]
    cudaGetSymbolAddress(&p_y1, g_y1);
    cudaGetSymbolAddress(&p_y2, g_y2);
    cudaGetSymbolAddress(&p_lg, g_logits);

    // 1. Z = emb[inputs] @ Wi + b  (time-parallel)
    embed_gemm_kernel<<<dim3(GATES / 128, (SEQ * BATCH) / 128), 256>>>(inputs, emb, Wi, bvec);

    // 2. persistent LSTM recurrence
    cudaFuncSetAttribute(lstm_kernel, cudaFuncAttributeMaxDynamicSharedMemorySize, LSTM_SMEM);
    lstm_kernel<<<NBLK, 256, LSTM_SMEM>>>(Wh);

    // 3/4. dense tanh layers (fc1 reads quarter-contiguous h)
    fc_tanh_kernel<1><<<BATCH, 512>>>((const float*)p_h,  W1, b1, (float*)p_y1);
    fc_tanh_kernel<0><<<BATCH, 512>>>((const float*)p_y1, W2, b2, (float*)p_y2);

    // 5. vocab projection
    logits_kernel<<<(VOCAB + 127) / 128, 128>>>((const float*)p_y2, W3, b3, (float*)p_lg);

    // 6. log_softmax
    logsoftmax_kernel<<<BATCH, 1024>>>((const float*)p_lg, out);
}